// round 8
// baseline (speedup 1.0000x reference)
#include <cuda_runtime.h>
#include <math.h>
#include <stdint.h>

#define NPTS 32768
#define DMODEL 256
#define NH 8
#define DHEAD 32
#define QKDIM 128
#define NLAYERS 5

// ---------------- static device scratch (no allocs allowed) ----------------
__device__ float g_fx[NPTS * DMODEL];
__device__ float g_t1[NPTS * DMODEL];
__device__ float g_t2[NPTS * DMODEL];
__device__ float g_t3[NPTS * DMODEL];
__device__ float g_hidden[NPTS * 512];
__device__ float g_kv2[NH * QKDIM * 40];   // [h][e][c], c=32 holds S
__device__ float g_kvh[NH * QKDIM * DHEAD];
__device__ float g_kvl[NH * QKDIM * DHEAD];
#define WCONV_PER 327680
__device__ float g_wc[5 * WCONV_PER + 131072];

__device__ __forceinline__ float gelu_f(float x) {
    return 0.5f * x * (1.0f + erff(x * 0.70710678118654752f));
}

__device__ __forceinline__ float to_tf32(float x) {
    uint32_t u;
    asm("cvt.rna.tf32.f32 %0, %1;" : "=r"(u) : "f"(x));
    return __uint_as_float(u);
}

// exp on the FMA pipe: 2^y with y = x*log2e; magic-number round, deg-5 poly, exp-bit add.
__device__ __forceinline__ float fast_exp(float x) {
    float y = fminf(fmaxf(x * 1.44269504f, -63.0f), 63.0f);
    float t = y + 12582912.0f;                    // round to nearest int (RN)
    int n = __float_as_int(t) - 0x4B400000;
    float f = y - (t - 12582912.0f);              // f in [-0.5, 0.5]
    float p =      1.3333558e-3f;
    p = fmaf(p, f, 9.6181291e-3f);
    p = fmaf(p, f, 5.5504109e-2f);
    p = fmaf(p, f, 2.4022651e-1f);
    p = fmaf(p, f, 6.9314718e-1f);
    p = fmaf(p, f, 1.0f);
    return __uint_as_float(__float_as_uint(p) + (n << 23));
}

__device__ __forceinline__ void mma_tf32(float* c, const uint32_t* a, const uint32_t* b) {
    asm volatile(
        "mma.sync.aligned.m16n8k8.row.col.f32.tf32.tf32.f32 "
        "{%0,%1,%2,%3}, {%4,%5,%6,%7}, {%8,%9}, {%0,%1,%2,%3};\n"
        : "+f"(c[0]), "+f"(c[1]), "+f"(c[2]), "+f"(c[3])
        : "r"(a[0]), "r"(a[1]), "r"(a[2]), "r"(a[3]), "r"(b[0]), "r"(b[1]));
}

__device__ __forceinline__ void cpa16(float* dst, const float* src) {
    uint32_t d = (uint32_t)__cvta_generic_to_shared(dst);
    asm volatile("cp.async.cg.shared.global [%0], [%1], 16;\n" :: "r"(d), "l"(src));
}

__device__ __forceinline__ float block_sum256(float v, volatile float* sh) {
    int lane = threadIdx.x & 31;
#pragma unroll
    for (int o = 16; o > 0; o >>= 1) v += __shfl_down_sync(0xffffffffu, v, o);
    if (lane == 0) sh[threadIdx.x >> 5] = v;
    __syncthreads();
    if (threadIdx.x < 32) {
        float r = (lane < 8) ? sh[lane] : 0.f;
#pragma unroll
        for (int o = 4; o > 0; o >>= 1) r += __shfl_down_sync(0xffffffffu, r, o);
        if (lane == 0) sh[0] = r;
    }
    __syncthreads();
    float out = sh[0];
    __syncthreads();
    return out;
}

// ---------------- tf32 weight conversion: 5 equal tensors in one launch ----------------
__global__ void conv5_tf32_kernel(const float* __restrict__ s0, const float* __restrict__ s1,
                                  const float* __restrict__ s2, const float* __restrict__ s3,
                                  const float* __restrict__ s4, float* __restrict__ dst) {
    const float* srcs[5] = {s0, s1, s2, s3, s4};
    int which = blockIdx.y;
    int i = blockIdx.x * 256 + threadIdx.x;
    if (i < WCONV_PER / 4) {
        float4 v = ((const float4*)srcs[which])[i];
        v.x = to_tf32(v.x); v.y = to_tf32(v.y);
        v.z = to_tf32(v.z); v.w = to_tf32(v.w);
        ((float4*)(dst + (size_t)which * WCONV_PER))[i] = v;
    }
}

__global__ void conv_tf32_kernel(const float* __restrict__ src, float* __restrict__ dst, int n4) {
    int i = blockIdx.x * 256 + threadIdx.x;
    if (i < n4) {
        float4 v = ((const float4*)src)[i];
        v.x = to_tf32(v.x); v.y = to_tf32(v.y);
        v.z = to_tf32(v.z); v.w = to_tf32(v.w);
        ((float4*)dst)[i] = v;
    }
}

// ---------------- preprocess: hidden = tf32(gelu(x @ pre_w1 + b1)) ----------------
__global__ void pre1_kernel(const float* __restrict__ x, const float* __restrict__ w1,
                            const float* __restrict__ b1, float* __restrict__ hidden) {
    int idx = blockIdx.x * 256 + threadIdx.x;
    int n = idx >> 9, j = idx & 511;
    float x0 = x[n * 3 + 0], x1 = x[n * 3 + 1], x2 = x[n * 3 + 2];
    float a = x0 * w1[j] + x1 * w1[512 + j] + x2 * w1[1024 + j] + b1[j];
    hidden[idx] = to_tf32(gelu_f(a));
}

// ---------------- tf32 tensor-core GEMM (R4 config: 256 thr, warp 64x32) ----------------
#define TBM 128
#define TBN 128
#define TBK 32
#define AS_STRIDE 36
#define BS_STRIDE 136
#define AS_FLOATS (TBM * AS_STRIDE)
#define BS_FLOATS (TBK * BS_STRIDE)
#define GEMM_SMEM_FLOATS (2 * (AS_FLOATS + BS_FLOATS))
__global__ __launch_bounds__(256, 2)
void gemm_kernel(const float* __restrict__ A, int K,
                 const float* __restrict__ W,
                 const float* __restrict__ bias,
                 const float* __restrict__ colbias,
                 const float* __restrict__ residual,
                 float* __restrict__ Y, int act, int rnd) {
    extern __shared__ float smem[];
    float* As = smem;
    float* Bs = smem + 2 * AS_FLOATS;

    int m0 = blockIdx.x * TBM;
    int n0 = blockIdx.y * TBN;
    int tid = threadIdx.x;
    int wid = tid >> 5, lane = tid & 31;
    int wm = (wid >> 2) * 64;
    int wn = (wid & 3) * 32;
    int lr = lane >> 2;
    int lc = lane & 3;

    float acc[4][4][4];
#pragma unroll
    for (int i = 0; i < 4; i++)
#pragma unroll
        for (int j = 0; j < 4; j++)
#pragma unroll
            for (int k = 0; k < 4; k++) acc[i][j][k] = 0.f;

    int a_r = tid >> 3;
    int a_kc = (tid & 7) * 4;
    int b_kr = tid >> 5;
    int b_nc = lane * 4;

    int nit = K / TBK;

    {
        float* as = As;
        float* bs = Bs;
#pragma unroll
        for (int rr = 0; rr < 4; rr++) {
            int row = a_r + rr * 32;
            cpa16(&as[row * AS_STRIDE + a_kc], A + (size_t)(m0 + row) * K + a_kc);
        }
#pragma unroll
        for (int kk = 0; kk < 4; kk++) {
            int krow = b_kr + kk * 8;
            cpa16(&bs[krow * BS_STRIDE + b_nc], W + (size_t)krow * DMODEL + n0 + b_nc);
        }
        asm volatile("cp.async.commit_group;\n");
    }

    for (int it = 0; it < nit; it++) {
        int cur = it & 1;
        if (it + 1 < nit) {
            int nxt = (it + 1) & 1;
            int k0 = (it + 1) * TBK;
            float* as = As + nxt * AS_FLOATS;
            float* bs = Bs + nxt * BS_FLOATS;
#pragma unroll
            for (int rr = 0; rr < 4; rr++) {
                int row = a_r + rr * 32;
                cpa16(&as[row * AS_STRIDE + a_kc], A + (size_t)(m0 + row) * K + k0 + a_kc);
            }
#pragma unroll
            for (int kk = 0; kk < 4; kk++) {
                int krow = b_kr + kk * 8;
                cpa16(&bs[krow * BS_STRIDE + b_nc], W + (size_t)(k0 + krow) * DMODEL + n0 + b_nc);
            }
            asm volatile("cp.async.commit_group;\n");
            asm volatile("cp.async.wait_group 1;\n");
        } else {
            asm volatile("cp.async.wait_group 0;\n");
        }
        __syncthreads();

        const float* as = As + cur * AS_FLOATS;
        const float* bs = Bs + cur * BS_FLOATS;
#pragma unroll
        for (int ks = 0; ks < TBK; ks += 8) {
            uint32_t af[4][4], bf[4][2];
#pragma unroll
            for (int mt = 0; mt < 4; mt++) {
                int r = wm + mt * 16 + lr;
                int c = ks + lc;
                af[mt][0] = __float_as_uint(as[r * AS_STRIDE + c]);
                af[mt][1] = __float_as_uint(as[(r + 8) * AS_STRIDE + c]);
                af[mt][2] = __float_as_uint(as[r * AS_STRIDE + c + 4]);
                af[mt][3] = __float_as_uint(as[(r + 8) * AS_STRIDE + c + 4]);
            }
#pragma unroll
            for (int nt = 0; nt < 4; nt++) {
                int n = wn + nt * 8 + lr;
                int c = ks + lc;
                bf[nt][0] = __float_as_uint(bs[c * BS_STRIDE + n]);
                bf[nt][1] = __float_as_uint(bs[(c + 4) * BS_STRIDE + n]);
            }
#pragma unroll
            for (int mt = 0; mt < 4; mt++)
#pragma unroll
                for (int nt = 0; nt < 4; nt++)
                    mma_tf32(acc[mt][nt], af[mt], bf[nt]);
        }
        __syncthreads();
    }

#pragma unroll
    for (int mt = 0; mt < 4; mt++) {
        int row = m0 + wm + mt * 16 + lr;
#pragma unroll
        for (int nt = 0; nt < 4; nt++) {
            int col = n0 + wn + nt * 8 + lc * 2;
#pragma unroll
            for (int half = 0; half < 2; half++) {
                int r = row + half * 8;
                float v0 = acc[mt][nt][half * 2 + 0];
                float v1 = acc[mt][nt][half * 2 + 1];
                if (bias)    { v0 += bias[col];        v1 += bias[col + 1]; }
                if (colbias) { v0 += colbias[col];     v1 += colbias[col + 1]; }
                if (act)     { v0 = gelu_f(v0);        v1 = gelu_f(v1); }
                if (residual) {
                    v0 += residual[(size_t)r * DMODEL + col];
                    v1 += residual[(size_t)r * DMODEL + col + 1];
                }
                if (rnd)     { v0 = to_tf32(v0);       v1 = to_tf32(v1); }
                float2 o; o.x = v0; o.y = v1;
                *(float2*)(Y + (size_t)r * DMODEL + col) = o;
            }
        }
    }
}

// ---------------- LayerNorm: warp per row, single pass, tf32-rounded output ----------------
__global__ void ln_kernel(const float* __restrict__ X, const float* __restrict__ g,
                          const float* __restrict__ b, float* __restrict__ Y) {
    int wid = threadIdx.x >> 5, lane = threadIdx.x & 31;
    int row = blockIdx.x * 8 + wid;
    const float4* X4 = (const float4*)(X + (size_t)row * DMODEL);
    const float4* G4 = (const float4*)g;
    const float4* B4 = (const float4*)b;
    float4* Y4 = (float4*)(Y + (size_t)row * DMODEL);

    float4 a = X4[lane];
    float4 c = X4[lane + 32];
    float s = a.x + a.y + a.z + a.w + c.x + c.y + c.z + c.w;
    float q = a.x * a.x + a.y * a.y + a.z * a.z + a.w * a.w
            + c.x * c.x + c.y * c.y + c.z * c.z + c.w * c.w;
#pragma unroll
    for (int o = 16; o > 0; o >>= 1) {
        s += __shfl_xor_sync(0xffffffffu, s, o);
        q += __shfl_xor_sync(0xffffffffu, q, o);
    }
    float mean = s * (1.0f / DMODEL);
    float var = q * (1.0f / DMODEL) - mean * mean;
    float rstd = rsqrtf(fmaxf(var, 0.f) + 1e-5f);

    float4 g1 = G4[lane], g2 = G4[lane + 32];
    float4 b1 = B4[lane], b2 = B4[lane + 32];
    float4 o1, o2;
    o1.x = to_tf32((a.x - mean) * rstd * g1.x + b1.x);
    o1.y = to_tf32((a.y - mean) * rstd * g1.y + b1.y);
    o1.z = to_tf32((a.z - mean) * rstd * g1.z + b1.z);
    o1.w = to_tf32((a.w - mean) * rstd * g1.w + b1.w);
    o2.x = to_tf32((c.x - mean) * rstd * g2.x + b2.x);
    o2.y = to_tf32((c.y - mean) * rstd * g2.y + b2.y);
    o2.z = to_tf32((c.z - mean) * rstd * g2.z + b2.z);
    o2.w = to_tf32((c.w - mean) * rstd * g2.w + b2.w);
    Y4[lane] = o1;
    Y4[lane + 32] = o2;
}

// ---------------- zero kv accumulators ----------------
__global__ void zero_kv_kernel() {
    int idx = blockIdx.x * 256 + threadIdx.x;
    if (idx < NH * QKDIM * 40) g_kv2[idx] = 0.f;
}

// ---------------- kvn: normalize kv by S, split hi/lo (once per layer) ----------------
__global__ void kvn_kernel(const float* __restrict__ kv2, float* __restrict__ kvh,
                           float* __restrict__ kvl) {
    int idx = blockIdx.x * 256 + threadIdx.x;  // NH*QKDIM*DHEAD = 32768
    int he = idx >> 5, c = idx & 31;
    float v = kv2[he * 40 + c] / kv2[he * 40 + 32];
    float hi = to_tf32(v);
    kvh[idx] = hi;
    kvl[idx] = to_tf32(v - hi);
}

// ================= tensor-core KV =================
// grid (128, NH): 256 rows/block in 4 chunks of 64
#define KV_SMEM_FLOATS (32*136 + 32*44 + 64*36 + 128*68 + 64*44)
__global__ void kv_mma_kernel(const float* __restrict__ xm, const float* __restrict__ wk,
                              const float* __restrict__ wv, const float* __restrict__ temp_k,
                              float* __restrict__ kvout) {
    extern __shared__ float sm[];
    float* wk_s = sm;
    float* wv_s = wk_s + 32 * 136;
    float* xm_s = wv_s + 32 * 44;
    float* kT_s = xm_s + 64 * 36;
    float* v_s  = kT_s + 128 * 68;

    int h = blockIdx.y;
    int tid = threadIdx.x;
    int wid = tid >> 5, lane = tid & 31;
    int lr = lane >> 2, lc = lane & 3;

    for (int i = tid; i < 32 * 128; i += 256) {
        int k = i >> 7, e = i & 127;
        wk_s[k * 136 + e] = to_tf32(wk[k * 128 + e]);
    }
    for (int i = tid; i < 32 * 32; i += 256) {
        int k = i >> 5, c = i & 31;
        wv_s[k * 44 + c] = to_tf32(wv[k * 32 + c]);
    }
    float itk = 1.0f / fminf(fmaxf(temp_k[h], 0.1f), 2.0f);

    float kvacc[5][4];
#pragma unroll
    for (int i = 0; i < 5; i++)
#pragma unroll
        for (int j = 0; j < 4; j++) kvacc[i][j] = 0.f;

    int row0 = blockIdx.x * 256;

    for (int ch = 0; ch < 4; ch++) {
        __syncthreads();
        {
            int r = tid >> 2, c0 = (tid & 3) * 8;
            const float* src = xm + (size_t)(row0 + ch * 64 + r) * DMODEL + h * DHEAD + c0;
            float4 v1 = *(const float4*)src, v2 = *(const float4*)(src + 4);
            float* dst = &xm_s[r * 36 + c0];
            dst[0] = v1.x; dst[1] = v1.y; dst[2] = v1.z; dst[3] = v1.w;
            dst[4] = v2.x; dst[5] = v2.y; dst[6] = v2.z; dst[7] = v2.w;
        }
        __syncthreads();

        {
            int wm = (wid & 3) * 16, wn = (wid >> 2) * 64;
            float acc[8][4];
#pragma unroll
            for (int i = 0; i < 8; i++)
#pragma unroll
                for (int j = 0; j < 4; j++) acc[i][j] = 0.f;
#pragma unroll
            for (int ks = 0; ks < 32; ks += 8) {
                uint32_t a[4];
                a[0] = __float_as_uint(xm_s[(wm + lr) * 36 + ks + lc]);
                a[1] = __float_as_uint(xm_s[(wm + lr + 8) * 36 + ks + lc]);
                a[2] = __float_as_uint(xm_s[(wm + lr) * 36 + ks + lc + 4]);
                a[3] = __float_as_uint(xm_s[(wm + lr + 8) * 36 + ks + lc + 4]);
#pragma unroll
                for (int nt = 0; nt < 8; nt++) {
                    uint32_t b[2];
                    b[0] = __float_as_uint(wk_s[(ks + lc) * 136 + wn + nt * 8 + lr]);
                    b[1] = __float_as_uint(wk_s[(ks + lc + 4) * 136 + wn + nt * 8 + lr]);
                    mma_tf32(acc[nt], a, b);
                }
            }
#pragma unroll
            for (int nt = 0; nt < 8; nt++) {
                int col = wn + nt * 8 + 2 * lc;
                int r = wm + lr;
                kT_s[col * 68 + r]           = to_tf32(fast_exp(acc[nt][0] * itk));
                kT_s[(col + 1) * 68 + r]     = to_tf32(fast_exp(acc[nt][1] * itk));
                kT_s[col * 68 + r + 8]       = to_tf32(fast_exp(acc[nt][2] * itk));
                kT_s[(col + 1) * 68 + r + 8] = to_tf32(fast_exp(acc[nt][3] * itk));
            }
        }
        if (wid < 4) {
            int wm = wid * 16;
            float acc[4][4];
#pragma unroll
            for (int i = 0; i < 4; i++)
#pragma unroll
                for (int j = 0; j < 4; j++) acc[i][j] = 0.f;
#pragma unroll
            for (int ks = 0; ks < 32; ks += 8) {
                uint32_t a[4];
                a[0] = __float_as_uint(xm_s[(wm + lr) * 36 + ks + lc]);
                a[1] = __float_as_uint(xm_s[(wm + lr + 8) * 36 + ks + lc]);
                a[2] = __float_as_uint(xm_s[(wm + lr) * 36 + ks + lc + 4]);
                a[3] = __float_as_uint(xm_s[(wm + lr + 8) * 36 + ks + lc + 4]);
#pragma unroll
                for (int nt = 0; nt < 4; nt++) {
                    uint32_t b[2];
                    b[0] = __float_as_uint(wv_s[(ks + lc) * 44 + nt * 8 + lr]);
                    b[1] = __float_as_uint(wv_s[(ks + lc + 4) * 44 + nt * 8 + lr]);
                    mma_tf32(acc[nt], a, b);
                }
            }
#pragma unroll
            for (int nt = 0; nt < 4; nt++) {
                int col = nt * 8 + 2 * lc;
                int r = wm + lr;
                v_s[r * 44 + col]           = to_tf32(acc[nt][0]);
                v_s[r * 44 + col + 1]       = to_tf32(acc[nt][1]);
                v_s[(r + 8) * 44 + col]     = to_tf32(acc[nt][2]);
                v_s[(r + 8) * 44 + col + 1] = to_tf32(acc[nt][3]);
            }
        }
        if (tid < 64) v_s[tid * 44 + 32] = 1.0f;
        __syncthreads();

        {
            int we = wid * 16;
#pragma unroll
            for (int ks = 0; ks < 64; ks += 8) {
                uint32_t a[4];
                a[0] = __float_as_uint(kT_s[(we + lr) * 68 + ks + lc]);
                a[1] = __float_as_uint(kT_s[(we + lr + 8) * 68 + ks + lc]);
                a[2] = __float_as_uint(kT_s[(we + lr) * 68 + ks + lc + 4]);
                a[3] = __float_as_uint(kT_s[(we + lr + 8) * 68 + ks + lc + 4]);
#pragma unroll
                for (int nt = 0; nt < 5; nt++) {
                    uint32_t b[2];
                    b[0] = __float_as_uint(v_s[(ks + lc) * 44 + nt * 8 + lr]);
                    b[1] = __float_as_uint(v_s[(ks + lc + 4) * 44 + nt * 8 + lr]);
                    mma_tf32(kvacc[nt], a, b);
                }
            }
        }
    }
    {
        int we = wid * 16;
#pragma unroll
        for (int nt = 0; nt < 5; nt++) {
            int col = nt * 8 + 2 * lc;
            int e0 = we + lr, e1 = we + lr + 8;
            if (col <= 32) {
                atomicAdd(&kvout[(h * QKDIM + e0) * 40 + col], kvacc[nt][0]);
                atomicAdd(&kvout[(h * QKDIM + e1) * 40 + col], kvacc[nt][2]);
            }
            if (col + 1 <= 32) {
                atomicAdd(&kvout[(h * QKDIM + e0) * 40 + col + 1], kvacc[nt][1]);
                atomicAdd(&kvout[(h * QKDIM + e1) * 40 + col + 1], kvacc[nt][3]);
            }
        }
    }
}

// ================= tensor-core QKV =================
#define QKV_SMEM_FLOATS (128*36*2 + 32*136 + 64*36 + 64*132)
__global__ void qkv_mma_kernel(const float* __restrict__ xm, const float* __restrict__ wq,
                               const float* __restrict__ temp_q,
                               const float* __restrict__ kvhg, const float* __restrict__ kvlg,
                               float* __restrict__ out) {
    extern __shared__ float sm[];
    float* kvh  = sm;
    float* kvl  = kvh + 128 * 36;
    float* wq_s = kvl + 128 * 36;
    float* xm_s = wq_s + 32 * 136;
    float* q_s  = xm_s + 64 * 36;

    int h = blockIdx.y;
    int row0 = blockIdx.x * 64;
    int tid = threadIdx.x;
    int wid = tid >> 5, lane = tid & 31;
    int lr = lane >> 2, lc = lane & 3;

    for (int i = tid; i < 32 * 128; i += 256) {
        int k = i >> 7, e = i & 127;
        wq_s[k * 136 + e] = to_tf32(wq[k * 128 + e]);
    }
    {
        const float4* hsrc = (const float4*)(kvhg + h * QKDIM * DHEAD);
        const float4* lsrc = (const float4*)(kvlg + h * QKDIM * DHEAD);
        for (int i = tid; i < 1024; i += 256) {
            int e = i >> 3, c4 = (i & 7) * 4;
            float4 hv = hsrc[i], lv = lsrc[i];
            *(float4*)(&kvh[e * 36 + c4]) = hv;
            *(float4*)(&kvl[e * 36 + c4]) = lv;
        }
    }
    {
        int r = tid >> 2, c0 = (tid & 3) * 8;
        const float* src = xm + (size_t)(row0 + r) * DMODEL + h * DHEAD + c0;
        float4 v1 = *(const float4*)src, v2 = *(const float4*)(src + 4);
        float* dst = &xm_s[r * 36 + c0];
        dst[0] = v1.x; dst[1] = v1.y; dst[2] = v1.z; dst[3] = v1.w;
        dst[4] = v2.x; dst[5] = v2.y; dst[6] = v2.z; dst[7] = v2.w;
    }
    float itq = 1.0f / fminf(fmaxf(temp_q[h], 0.1f), 2.0f);
    __syncthreads();

    {
        int wm = (wid & 3) * 16, wn = (wid >> 2) * 64;
        float acc[8][4];
#pragma unroll
        for (int i = 0; i < 8; i++)
#pragma unroll
            for (int j = 0; j < 4; j++) acc[i][j] = 0.f;
#pragma unroll
        for (int ks = 0; ks < 32; ks += 8) {
            uint32_t a[4];
            a[0] = __float_as_uint(xm_s[(wm + lr) * 36 + ks + lc]);
            a[1] = __float_as_uint(xm_s[(wm + lr + 8) * 36 + ks + lc]);
            a[2] = __float_as_uint(xm_s[(wm + lr) * 36 + ks + lc + 4]);
            a[3] = __float_as_uint(xm_s[(wm + lr + 8) * 36 + ks + lc + 4]);
#pragma unroll
            for (int nt = 0; nt < 8; nt++) {
                uint32_t b[2];
                b[0] = __float_as_uint(wq_s[(ks + lc) * 136 + wn + nt * 8 + lr]);
                b[1] = __float_as_uint(wq_s[(ks + lc + 4) * 136 + wn + nt * 8 + lr]);
                mma_tf32(acc[nt], a, b);
            }
        }
#pragma unroll
        for (int nt = 0; nt < 8; nt++) {
            int col = wn + nt * 8 + 2 * lc;
            int r = wm + lr;
            q_s[r * 132 + col]           = acc[nt][0] * itq;
            q_s[r * 132 + col + 1]       = acc[nt][1] * itq;
            q_s[(r + 8) * 132 + col]     = acc[nt][2] * itq;
            q_s[(r + 8) * 132 + col + 1] = acc[nt][3] * itq;
        }
    }
    __syncthreads();
    {   // max-free softmax over 128 (division by sum normalizes; logits are small)
        int r = tid >> 2, sub = tid & 3;
        float* row = q_s + r * 132;
        float ev[32], sum = 0.f;
#pragma unroll
        for (int k = 0; k < 32; k++) { ev[k] = fast_exp(row[sub + k * 4]); sum += ev[k]; }
        sum += __shfl_xor_sync(0xffffffffu, sum, 1);
        sum += __shfl_xor_sync(0xffffffffu, sum, 2);
        float inv = 1.0f / sum;
#pragma unroll
        for (int k = 0; k < 32; k++) row[sub + k * 4] = to_tf32(ev[k] * inv);
    }
    __syncthreads();
    {
        int wm = (wid & 3) * 16;
        int part = wid >> 2;
        const float* kvp = part ? kvl : kvh;
        float acc[4][4];
#pragma unroll
        for (int i = 0; i < 4; i++)
#pragma unroll
            for (int j = 0; j < 4; j++) acc[i][j] = 0.f;
#pragma unroll
        for (int ks = 0; ks < 128; ks += 8) {
            uint32_t a[4];
            a[0] = __float_as_uint(q_s[(wm + lr) * 132 + ks + lc]);
            a[1] = __float_as_uint(q_s[(wm + lr + 8) * 132 + ks + lc]);
            a[2] = __float_as_uint(q_s[(wm + lr) * 132 + ks + lc + 4]);
            a[3] = __float_as_uint(q_s[(wm + lr + 8) * 132 + ks + lc + 4]);
#pragma unroll
            for (int nt = 0; nt < 4; nt++) {
                uint32_t b[2];
                b[0] = __float_as_uint(kvp[(ks + lc) * 36 + nt * 8 + lr]);
                b[1] = __float_as_uint(kvp[(ks + lc + 4) * 36 + nt * 8 + lr]);
                mma_tf32(acc[nt], a, b);
            }
        }
        if (part == 1) {
#pragma unroll
            for (int nt = 0; nt < 4; nt++) {
                int col = nt * 8 + 2 * lc;
                int r = wm + lr;
                xm_s[r * 36 + col]           = acc[nt][0];
                xm_s[r * 36 + col + 1]       = acc[nt][1];
                xm_s[(r + 8) * 36 + col]     = acc[nt][2];
                xm_s[(r + 8) * 36 + col + 1] = acc[nt][3];
            }
        }
        __syncthreads();
        if (part == 0) {
#pragma unroll
            for (int nt = 0; nt < 4; nt++) {
                int col = nt * 8 + 2 * lc;
#pragma unroll
                for (int half = 0; half < 2; half++) {
                    int r = wm + lr + half * 8;
                    float v0 = to_tf32(acc[nt][half * 2 + 0] + xm_s[r * 36 + col]);
                    float v1 = to_tf32(acc[nt][half * 2 + 1] + xm_s[r * 36 + col + 1]);
                    float2 o; o.x = v0; o.y = v1;
                    *(float2*)(out + (size_t)(row0 + r) * DMODEL + h * DHEAD + col) = o;
                }
            }
        }
    }
}

// ---------------- head: out[n] = LN(fx) @ head_w + head_b ----------------
__global__ void head_kernel(const float* __restrict__ fx, const float* __restrict__ g,
                            const float* __restrict__ b, const float* __restrict__ hw,
                            const float* __restrict__ hb, float* __restrict__ out) {
    __shared__ float sh[8];
    int n = blockIdx.x, t = threadIdx.x;
    float v = fx[(size_t)n * DMODEL + t];
    float mean = block_sum256(v, sh) * (1.0f / DMODEL);
    float d = v - mean;
    float var = block_sum256(d * d, sh) * (1.0f / DMODEL);
    float rstd = rsqrtf(var + 1e-5f);
    float hn = d * rstd * g[t] + b[t];
    float dot = block_sum256(hn * hw[t], sh);
    if (t == 0) out[n] = dot + hb[0];
}

// ---------------- launch ----------------
extern "C" void kernel_launch(void* const* d_in, const int* in_sizes, int n_in,
                              void* d_out, int out_size) {
    const float* x          = (const float*)d_in[0];
    const float* pre_w1     = (const float*)d_in[1];
    const float* pre_b1     = (const float*)d_in[2];
    const float* pre_w2     = (const float*)d_in[3];
    const float* pre_b2     = (const float*)d_in[4];
    const float* placeholder= (const float*)d_in[5];
    const float* ln1_g      = (const float*)d_in[6];
    const float* ln1_b      = (const float*)d_in[7];
    const float* inp_w      = (const float*)d_in[8];
    const float* inp_b      = (const float*)d_in[9];
    const float* temp_q     = (const float*)d_in[10];
    const float* temp_k     = (const float*)d_in[11];
    const float* wq         = (const float*)d_in[12];
    const float* wk         = (const float*)d_in[13];
    const float* wv         = (const float*)d_in[14];
    const float* out_w1     = (const float*)d_in[15];
    const float* out_b1     = (const float*)d_in[16];
    const float* out_w2     = (const float*)d_in[17];
    const float* out_b2     = (const float*)d_in[18];
    const float* ln2_g      = (const float*)d_in[19];
    const float* ln2_b      = (const float*)d_in[20];
    const float* mlp_w1     = (const float*)d_in[21];
    const float* mlp_b1     = (const float*)d_in[22];
    const float* mlp_w2     = (const float*)d_in[23];
    const float* mlp_b2     = (const float*)d_in[24];
    const float* ln3_g      = (const float*)d_in[25];
    const float* ln3_b      = (const float*)d_in[26];
    const float* head_w     = (const float*)d_in[27];
    const float* head_b     = (const float*)d_in[28];

    float *fx, *t1, *t2, *t3, *hidden, *kv2, *kvh, *kvl, *wc;
    cudaGetSymbolAddress((void**)&fx, g_fx);
    cudaGetSymbolAddress((void**)&t1, g_t1);
    cudaGetSymbolAddress((void**)&t2, g_t2);
    cudaGetSymbolAddress((void**)&t3, g_t3);
    cudaGetSymbolAddress((void**)&hidden, g_hidden);
    cudaGetSymbolAddress((void**)&kv2, g_kv2);
    cudaGetSymbolAddress((void**)&kvh, g_kvh);
    cudaGetSymbolAddress((void**)&kvl, g_kvl);
    cudaGetSymbolAddress((void**)&wc, g_wc);

    float* iwc   = wc;
    float* ow1c  = wc + 1 * WCONV_PER;
    float* ow2c  = wc + 2 * WCONV_PER;
    float* mw1c  = wc + 3 * WCONV_PER;
    float* mw2c  = wc + 4 * WCONV_PER;
    float* pw2c  = wc + 5 * WCONV_PER;

    const int gemm_smem = GEMM_SMEM_FLOATS * 4;
    const int kv_smem = KV_SMEM_FLOATS * 4;
    const int qkv_smem = QKV_SMEM_FLOATS * 4;
    cudaFuncSetAttribute(gemm_kernel, cudaFuncAttributeMaxDynamicSharedMemorySize, gemm_smem);
    cudaFuncSetAttribute(kv_mma_kernel, cudaFuncAttributeMaxDynamicSharedMemorySize, kv_smem);
    cudaFuncSetAttribute(qkv_mma_kernel, cudaFuncAttributeMaxDynamicSharedMemorySize, qkv_smem);

    dim3 ggrid(NPTS / TBM, DMODEL / TBN);

    conv5_tf32_kernel<<<dim3((WCONV_PER / 4 + 255) / 256, 5), 256>>>(inp_w, out_w1, out_w2,
                                                                     mlp_w1, mlp_w2, wc);
    conv_tf32_kernel<<<(131072 / 4 + 255) / 256, 256>>>(pre_w2, pw2c, 131072 / 4);

    pre1_kernel<<<NPTS * 512 / 256, 256>>>(x, pre_w1, pre_b1, hidden);
    gemm_kernel<<<ggrid, 256, gemm_smem>>>(hidden, 512, pw2c, pre_b2, placeholder, nullptr, fx, 0, 0);

    for (int i = 0; i < NLAYERS; i++) {
        const float* iw  = iwc  + (size_t)i * 65536;
        const float* ow1 = ow1c + (size_t)i * 65536;
        const float* ow2 = ow2c + (size_t)i * 65536;
        const float* mw1 = mw1c + (size_t)i * 65536;
        const float* mw2 = mw2c + (size_t)i * 65536;

        ln_kernel<<<NPTS / 8, 256>>>(fx, ln1_g + i * 256, ln1_b + i * 256, t1);
        gemm_kernel<<<ggrid, 256, gemm_smem>>>(t1, 256, iw, inp_b + i * 256, nullptr, nullptr, t2, 0, 1);
        zero_kv_kernel<<<(NH * QKDIM * 40 + 255) / 256, 256>>>();
        kv_mma_kernel<<<dim3(128, NH), 256, kv_smem>>>(t2, wk + (size_t)i * 4096,
                                                       wv + (size_t)i * 1024, temp_k + i * NH, kv2);
        kvn_kernel<<<(NH * QKDIM * DHEAD + 255) / 256, 256>>>(kv2, kvh, kvl);
        qkv_mma_kernel<<<dim3(NPTS / 64, NH), 256, qkv_smem>>>(t2, wq + (size_t)i * 4096,
                                                               temp_q + i * NH, kvh, kvl, t3);
        gemm_kernel<<<ggrid, 256, gemm_smem>>>(t3, 256, ow1, out_b1 + i * 256, nullptr, nullptr, t1, 1, 1);
        gemm_kernel<<<ggrid, 256, gemm_smem>>>(t1, 256, ow2, out_b2 + i * 256, nullptr, fx, fx, 0, 0);
        ln_kernel<<<NPTS / 8, 256>>>(fx, ln2_g + i * 256, ln2_b + i * 256, t1);
        gemm_kernel<<<ggrid, 256, gemm_smem>>>(t1, 256, mw1, mlp_b1 + i * 256, nullptr, nullptr, t2, 1, 1);
        gemm_kernel<<<ggrid, 256, gemm_smem>>>(t2, 256, mw2, mlp_b2 + i * 256, nullptr, fx, fx, 0, 0);
    }
    head_kernel<<<NPTS, 256>>>(fx, ln3_g, ln3_b, head_w, head_b, (float*)d_out);
}

// round 9
// speedup vs baseline: 1.0635x; 1.0635x over previous
#include <cuda_runtime.h>
#include <math.h>
#include <stdint.h>

#define NPTS 32768
#define DMODEL 256
#define NH 8
#define DHEAD 32
#define QKDIM 128
#define NLAYERS 5
#define KVBLK 32

// ---------------- static device scratch (no allocs allowed) ----------------
__device__ float g_fx[NPTS * DMODEL];
__device__ float g_t1[NPTS * DMODEL];
__device__ float g_t2[NPTS * DMODEL];
__device__ float g_t3[NPTS * DMODEL];
__device__ float g_hidden[NPTS * 512];
__device__ float g_kvp[KVBLK * NH * QKDIM * 40];  // per-block partials, col 32 = S
__device__ float g_kvh[NH * QKDIM * DHEAD];
__device__ float g_kvl[NH * QKDIM * DHEAD];
#define WCONV_PER 327680
__device__ float g_wc[5 * WCONV_PER + 131072];

__device__ __forceinline__ float gelu_f(float x) {
    return 0.5f * x * (1.0f + erff(x * 0.70710678118654752f));
}

__device__ __forceinline__ float to_tf32(float x) {
    uint32_t u;
    asm("cvt.rna.tf32.f32 %0, %1;" : "=r"(u) : "f"(x));
    return __uint_as_float(u);
}

__device__ __forceinline__ void mma_tf32(float* c, const uint32_t* a, const uint32_t* b) {
    asm volatile(
        "mma.sync.aligned.m16n8k8.row.col.f32.tf32.tf32.f32 "
        "{%0,%1,%2,%3}, {%4,%5,%6,%7}, {%8,%9}, {%0,%1,%2,%3};\n"
        : "+f"(c[0]), "+f"(c[1]), "+f"(c[2]), "+f"(c[3])
        : "r"(a[0]), "r"(a[1]), "r"(a[2]), "r"(a[3]), "r"(b[0]), "r"(b[1]));
}

__device__ __forceinline__ void cpa16(float* dst, const float* src) {
    uint32_t d = (uint32_t)__cvta_generic_to_shared(dst);
    asm volatile("cp.async.cg.shared.global [%0], [%1], 16;\n" :: "r"(d), "l"(src));
}

__device__ __forceinline__ float block_sum256(float v, volatile float* sh) {
    int lane = threadIdx.x & 31;
#pragma unroll
    for (int o = 16; o > 0; o >>= 1) v += __shfl_down_sync(0xffffffffu, v, o);
    if (lane == 0) sh[threadIdx.x >> 5] = v;
    __syncthreads();
    if (threadIdx.x < 32) {
        float r = (lane < 8) ? sh[lane] : 0.f;
#pragma unroll
        for (int o = 4; o > 0; o >>= 1) r += __shfl_down_sync(0xffffffffu, r, o);
        if (lane == 0) sh[0] = r;
    }
    __syncthreads();
    float out = sh[0];
    __syncthreads();
    return out;
}

// ---------------- tf32 weight conversion: 5 equal tensors in one launch ----------------
__global__ void conv5_tf32_kernel(const float* __restrict__ s0, const float* __restrict__ s1,
                                  const float* __restrict__ s2, const float* __restrict__ s3,
                                  const float* __restrict__ s4, float* __restrict__ dst) {
    const float* srcs[5] = {s0, s1, s2, s3, s4};
    int which = blockIdx.y;
    int i = blockIdx.x * 256 + threadIdx.x;
    if (i < WCONV_PER / 4) {
        float4 v = ((const float4*)srcs[which])[i];
        v.x = to_tf32(v.x); v.y = to_tf32(v.y);
        v.z = to_tf32(v.z); v.w = to_tf32(v.w);
        ((float4*)(dst + (size_t)which * WCONV_PER))[i] = v;
    }
}

__global__ void conv_tf32_kernel(const float* __restrict__ src, float* __restrict__ dst, int n4) {
    int i = blockIdx.x * 256 + threadIdx.x;
    if (i < n4) {
        float4 v = ((const float4*)src)[i];
        v.x = to_tf32(v.x); v.y = to_tf32(v.y);
        v.z = to_tf32(v.z); v.w = to_tf32(v.w);
        ((float4*)dst)[i] = v;
    }
}

// ---------------- preprocess: hidden = tf32(gelu(x @ pre_w1 + b1)) ----------------
__global__ void pre1_kernel(const float* __restrict__ x, const float* __restrict__ w1,
                            const float* __restrict__ b1, float* __restrict__ hidden) {
    int idx = blockIdx.x * 256 + threadIdx.x;
    int n = idx >> 9, j = idx & 511;
    float x0 = x[n * 3 + 0], x1 = x[n * 3 + 1], x2 = x[n * 3 + 2];
    float a = x0 * w1[j] + x1 * w1[512 + j] + x2 * w1[1024 + j] + b1[j];
    hidden[idx] = to_tf32(gelu_f(a));
}

// ---------------- tf32 tensor-core GEMM (R4 config: 256 thr, warp 64x32) ----------------
#define TBM 128
#define TBN 128
#define TBK 32
#define AS_STRIDE 36
#define BS_STRIDE 136
#define AS_FLOATS (TBM * AS_STRIDE)
#define BS_FLOATS (TBK * BS_STRIDE)
#define GEMM_SMEM_FLOATS (2 * (AS_FLOATS + BS_FLOATS))
__global__ __launch_bounds__(256, 2)
void gemm_kernel(const float* __restrict__ A, int K,
                 const float* __restrict__ W,
                 const float* __restrict__ bias,
                 const float* __restrict__ colbias,
                 const float* __restrict__ residual,
                 float* __restrict__ Y, int act, int rnd) {
    extern __shared__ float smem[];
    float* As = smem;
    float* Bs = smem + 2 * AS_FLOATS;

    int m0 = blockIdx.x * TBM;
    int n0 = blockIdx.y * TBN;
    int tid = threadIdx.x;
    int wid = tid >> 5, lane = tid & 31;
    int wm = (wid >> 2) * 64;
    int wn = (wid & 3) * 32;
    int lr = lane >> 2;
    int lc = lane & 3;

    float acc[4][4][4];
#pragma unroll
    for (int i = 0; i < 4; i++)
#pragma unroll
        for (int j = 0; j < 4; j++)
#pragma unroll
            for (int k = 0; k < 4; k++) acc[i][j][k] = 0.f;

    int a_r = tid >> 3;
    int a_kc = (tid & 7) * 4;
    int b_kr = tid >> 5;
    int b_nc = lane * 4;

    int nit = K / TBK;

    {
        float* as = As;
        float* bs = Bs;
#pragma unroll
        for (int rr = 0; rr < 4; rr++) {
            int row = a_r + rr * 32;
            cpa16(&as[row * AS_STRIDE + a_kc], A + (size_t)(m0 + row) * K + a_kc);
        }
#pragma unroll
        for (int kk = 0; kk < 4; kk++) {
            int krow = b_kr + kk * 8;
            cpa16(&bs[krow * BS_STRIDE + b_nc], W + (size_t)krow * DMODEL + n0 + b_nc);
        }
        asm volatile("cp.async.commit_group;\n");
    }

    for (int it = 0; it < nit; it++) {
        int cur = it & 1;
        if (it + 1 < nit) {
            int nxt = (it + 1) & 1;
            int k0 = (it + 1) * TBK;
            float* as = As + nxt * AS_FLOATS;
            float* bs = Bs + nxt * BS_FLOATS;
#pragma unroll
            for (int rr = 0; rr < 4; rr++) {
                int row = a_r + rr * 32;
                cpa16(&as[row * AS_STRIDE + a_kc], A + (size_t)(m0 + row) * K + k0 + a_kc);
            }
#pragma unroll
            for (int kk = 0; kk < 4; kk++) {
                int krow = b_kr + kk * 8;
                cpa16(&bs[krow * BS_STRIDE + b_nc], W + (size_t)(k0 + krow) * DMODEL + n0 + b_nc);
            }
            asm volatile("cp.async.commit_group;\n");
            asm volatile("cp.async.wait_group 1;\n");
        } else {
            asm volatile("cp.async.wait_group 0;\n");
        }
        __syncthreads();

        const float* as = As + cur * AS_FLOATS;
        const float* bs = Bs + cur * BS_FLOATS;
#pragma unroll
        for (int ks = 0; ks < TBK; ks += 8) {
            uint32_t af[4][4], bf[4][2];
#pragma unroll
            for (int mt = 0; mt < 4; mt++) {
                int r = wm + mt * 16 + lr;
                int c = ks + lc;
                af[mt][0] = __float_as_uint(as[r * AS_STRIDE + c]);
                af[mt][1] = __float_as_uint(as[(r + 8) * AS_STRIDE + c]);
                af[mt][2] = __float_as_uint(as[r * AS_STRIDE + c + 4]);
                af[mt][3] = __float_as_uint(as[(r + 8) * AS_STRIDE + c + 4]);
            }
#pragma unroll
            for (int nt = 0; nt < 4; nt++) {
                int n = wn + nt * 8 + lr;
                int c = ks + lc;
                bf[nt][0] = __float_as_uint(bs[c * BS_STRIDE + n]);
                bf[nt][1] = __float_as_uint(bs[(c + 4) * BS_STRIDE + n]);
            }
#pragma unroll
            for (int mt = 0; mt < 4; mt++)
#pragma unroll
                for (int nt = 0; nt < 4; nt++)
                    mma_tf32(acc[mt][nt], af[mt], bf[nt]);
        }
        __syncthreads();
    }

#pragma unroll
    for (int mt = 0; mt < 4; mt++) {
        int row = m0 + wm + mt * 16 + lr;
#pragma unroll
        for (int nt = 0; nt < 4; nt++) {
            int col = n0 + wn + nt * 8 + lc * 2;
#pragma unroll
            for (int half = 0; half < 2; half++) {
                int r = row + half * 8;
                float v0 = acc[mt][nt][half * 2 + 0];
                float v1 = acc[mt][nt][half * 2 + 1];
                if (bias)    { v0 += bias[col];        v1 += bias[col + 1]; }
                if (colbias) { v0 += colbias[col];     v1 += colbias[col + 1]; }
                if (act)     { v0 = gelu_f(v0);        v1 = gelu_f(v1); }
                if (residual) {
                    v0 += residual[(size_t)r * DMODEL + col];
                    v1 += residual[(size_t)r * DMODEL + col + 1];
                }
                if (rnd)     { v0 = to_tf32(v0);       v1 = to_tf32(v1); }
                float2 o; o.x = v0; o.y = v1;
                *(float2*)(Y + (size_t)r * DMODEL + col) = o;
            }
        }
    }
}

// ---------------- LayerNorm: warp per row, single pass, tf32-rounded output ----------------
__global__ void ln_kernel(const float* __restrict__ X, const float* __restrict__ g,
                          const float* __restrict__ b, float* __restrict__ Y) {
    int wid = threadIdx.x >> 5, lane = threadIdx.x & 31;
    int row = blockIdx.x * 8 + wid;
    const float4* X4 = (const float4*)(X + (size_t)row * DMODEL);
    const float4* G4 = (const float4*)g;
    const float4* B4 = (const float4*)b;
    float4* Y4 = (float4*)(Y + (size_t)row * DMODEL);

    float4 a = X4[lane];
    float4 c = X4[lane + 32];
    float s = a.x + a.y + a.z + a.w + c.x + c.y + c.z + c.w;
    float q = a.x * a.x + a.y * a.y + a.z * a.z + a.w * a.w
            + c.x * c.x + c.y * c.y + c.z * c.z + c.w * c.w;
#pragma unroll
    for (int o = 16; o > 0; o >>= 1) {
        s += __shfl_xor_sync(0xffffffffu, s, o);
        q += __shfl_xor_sync(0xffffffffu, q, o);
    }
    float mean = s * (1.0f / DMODEL);
    float var = q * (1.0f / DMODEL) - mean * mean;
    float rstd = rsqrtf(fmaxf(var, 0.f) + 1e-5f);

    float4 g1 = G4[lane], g2 = G4[lane + 32];
    float4 b1 = B4[lane], b2 = B4[lane + 32];
    float4 o1, o2;
    o1.x = to_tf32((a.x - mean) * rstd * g1.x + b1.x);
    o1.y = to_tf32((a.y - mean) * rstd * g1.y + b1.y);
    o1.z = to_tf32((a.z - mean) * rstd * g1.z + b1.z);
    o1.w = to_tf32((a.w - mean) * rstd * g1.w + b1.w);
    o2.x = to_tf32((c.x - mean) * rstd * g2.x + b2.x);
    o2.y = to_tf32((c.y - mean) * rstd * g2.y + b2.y);
    o2.z = to_tf32((c.z - mean) * rstd * g2.z + b2.z);
    o2.w = to_tf32((c.w - mean) * rstd * g2.w + b2.w);
    Y4[lane] = o1;
    Y4[lane + 32] = o2;
}

// ---------------- kvn: reduce 32 partials, normalize by S, split hi/lo ----------------
__global__ void kvn_kernel(const float* __restrict__ kvp, float* __restrict__ kvh,
                           float* __restrict__ kvl) {
    int idx = blockIdx.x * 256 + threadIdx.x;  // NH*QKDIM*DHEAD = 32768
    int he = idx >> 5, c = idx & 31;
    float sv = 0.f, ss = 0.f;
    const float* base = kvp + (size_t)he * 40;
#pragma unroll 4
    for (int b = 0; b < KVBLK; b++) {
        const float* p = base + (size_t)b * NH * QKDIM * 40;
        sv += p[c];
        ss += p[32];
    }
    float v = sv / ss;
    float hi = to_tf32(v);
    kvh[idx] = hi;
    kvl[idx] = to_tf32(v - hi);
}

// ================= tensor-core KV =================
// grid (32, NH), 1024 rows/block in 16 chunks of 64; partials out (no atomics)
#define KV_SMEM_FLOATS (32*136 + 32*44 + 64*36 + 128*68 + 64*44)
__global__ void kv_mma_kernel(const float* __restrict__ xm, const float* __restrict__ wk,
                              const float* __restrict__ wv, const float* __restrict__ temp_k,
                              float* __restrict__ kvp) {
    extern __shared__ float sm[];
    float* wk_s = sm;
    float* wv_s = wk_s + 32 * 136;
    float* xm_s = wv_s + 32 * 44;
    float* kT_s = xm_s + 64 * 36;
    float* v_s  = kT_s + 128 * 68;

    int h = blockIdx.y;
    int tid = threadIdx.x;
    int wid = tid >> 5, lane = tid & 31;
    int lr = lane >> 2, lc = lane & 3;

    for (int i = tid; i < 32 * 128; i += 256) {
        int k = i >> 7, e = i & 127;
        wk_s[k * 136 + e] = to_tf32(wk[k * 128 + e]);
    }
    for (int i = tid; i < 32 * 32; i += 256) {
        int k = i >> 5, c = i & 31;
        wv_s[k * 44 + c] = to_tf32(wv[k * 32 + c]);
    }
    float itk = 1.0f / fminf(fmaxf(temp_k[h], 0.1f), 2.0f);

    float kvacc[5][4];
#pragma unroll
    for (int i = 0; i < 5; i++)
#pragma unroll
        for (int j = 0; j < 4; j++) kvacc[i][j] = 0.f;

    int row0 = blockIdx.x * 1024;

    for (int ch = 0; ch < 16; ch++) {
        __syncthreads();
        {
            int r = tid >> 2, c0 = (tid & 3) * 8;
            const float* src = xm + (size_t)(row0 + ch * 64 + r) * DMODEL + h * DHEAD + c0;
            float4 v1 = *(const float4*)src, v2 = *(const float4*)(src + 4);
            float* dst = &xm_s[r * 36 + c0];
            dst[0] = v1.x; dst[1] = v1.y; dst[2] = v1.z; dst[3] = v1.w;
            dst[4] = v2.x; dst[5] = v2.y; dst[6] = v2.z; dst[7] = v2.w;
        }
        __syncthreads();

        {
            int wm = (wid & 3) * 16, wn = (wid >> 2) * 64;
            float acc[8][4];
#pragma unroll
            for (int i = 0; i < 8; i++)
#pragma unroll
                for (int j = 0; j < 4; j++) acc[i][j] = 0.f;
#pragma unroll
            for (int ks = 0; ks < 32; ks += 8) {
                uint32_t a[4];
                a[0] = __float_as_uint(xm_s[(wm + lr) * 36 + ks + lc]);
                a[1] = __float_as_uint(xm_s[(wm + lr + 8) * 36 + ks + lc]);
                a[2] = __float_as_uint(xm_s[(wm + lr) * 36 + ks + lc + 4]);
                a[3] = __float_as_uint(xm_s[(wm + lr + 8) * 36 + ks + lc + 4]);
#pragma unroll
                for (int nt = 0; nt < 8; nt++) {
                    uint32_t b[2];
                    b[0] = __float_as_uint(wk_s[(ks + lc) * 136 + wn + nt * 8 + lr]);
                    b[1] = __float_as_uint(wk_s[(ks + lc + 4) * 136 + wn + nt * 8 + lr]);
                    mma_tf32(acc[nt], a, b);
                }
            }
#pragma unroll
            for (int nt = 0; nt < 8; nt++) {
                int col = wn + nt * 8 + 2 * lc;
                int r = wm + lr;
                kT_s[col * 68 + r]           = to_tf32(__expf(acc[nt][0] * itk));
                kT_s[(col + 1) * 68 + r]     = to_tf32(__expf(acc[nt][1] * itk));
                kT_s[col * 68 + r + 8]       = to_tf32(__expf(acc[nt][2] * itk));
                kT_s[(col + 1) * 68 + r + 8] = to_tf32(__expf(acc[nt][3] * itk));
            }
        }
        if (wid < 4) {
            int wm = wid * 16;
            float acc[4][4];
#pragma unroll
            for (int i = 0; i < 4; i++)
#pragma unroll
                for (int j = 0; j < 4; j++) acc[i][j] = 0.f;
#pragma unroll
            for (int ks = 0; ks < 32; ks += 8) {
                uint32_t a[4];
                a[0] = __float_as_uint(xm_s[(wm + lr) * 36 + ks + lc]);
                a[1] = __float_as_uint(xm_s[(wm + lr + 8) * 36 + ks + lc]);
                a[2] = __float_as_uint(xm_s[(wm + lr) * 36 + ks + lc + 4]);
                a[3] = __float_as_uint(xm_s[(wm + lr + 8) * 36 + ks + lc + 4]);
#pragma unroll
                for (int nt = 0; nt < 4; nt++) {
                    uint32_t b[2];
                    b[0] = __float_as_uint(wv_s[(ks + lc) * 44 + nt * 8 + lr]);
                    b[1] = __float_as_uint(wv_s[(ks + lc + 4) * 44 + nt * 8 + lr]);
                    mma_tf32(acc[nt], a, b);
                }
            }
#pragma unroll
            for (int nt = 0; nt < 4; nt++) {
                int col = nt * 8 + 2 * lc;
                int r = wm + lr;
                v_s[r * 44 + col]           = to_tf32(acc[nt][0]);
                v_s[r * 44 + col + 1]       = to_tf32(acc[nt][1]);
                v_s[(r + 8) * 44 + col]     = to_tf32(acc[nt][2]);
                v_s[(r + 8) * 44 + col + 1] = to_tf32(acc[nt][3]);
            }
        }
        if (tid < 64) v_s[tid * 44 + 32] = 1.0f;
        __syncthreads();

        {
            int we = wid * 16;
#pragma unroll
            for (int ks = 0; ks < 64; ks += 8) {
                uint32_t a[4];
                a[0] = __float_as_uint(kT_s[(we + lr) * 68 + ks + lc]);
                a[1] = __float_as_uint(kT_s[(we + lr + 8) * 68 + ks + lc]);
                a[2] = __float_as_uint(kT_s[(we + lr) * 68 + ks + lc + 4]);
                a[3] = __float_as_uint(kT_s[(we + lr + 8) * 68 + ks + lc + 4]);
#pragma unroll
                for (int nt = 0; nt < 5; nt++) {
                    uint32_t b[2];
                    b[0] = __float_as_uint(v_s[(ks + lc) * 44 + nt * 8 + lr]);
                    b[1] = __float_as_uint(v_s[(ks + lc + 4) * 44 + nt * 8 + lr]);
                    mma_tf32(kvacc[nt], a, b);
                }
            }
        }
    }
    {   // flush partials (no atomics): kvp[(bid*NH + h)*QKDIM + e)*40 + col]
        float* dst = kvp + (size_t)(blockIdx.x * NH + h) * QKDIM * 40;
        int we = wid * 16;
#pragma unroll
        for (int nt = 0; nt < 5; nt++) {
            int col = nt * 8 + 2 * lc;
            int e0 = we + lr, e1 = we + lr + 8;
            if (col <= 32) {
                dst[e0 * 40 + col] = kvacc[nt][0];
                dst[e1 * 40 + col] = kvacc[nt][2];
            }
            if (col + 1 <= 32) {
                dst[e0 * 40 + col + 1] = kvacc[nt][1];
                dst[e1 * 40 + col + 1] = kvacc[nt][3];
            }
        }
    }
}

// ================= tensor-core QKV: 128 rows/block in 2 chunks =================
#define QKV_SMEM_FLOATS (128*36*2 + 32*136 + 64*36 + 64*132)
__global__ void qkv_mma_kernel(const float* __restrict__ xm, const float* __restrict__ wq,
                               const float* __restrict__ temp_q,
                               const float* __restrict__ kvhg, const float* __restrict__ kvlg,
                               float* __restrict__ out) {
    extern __shared__ float sm[];
    float* kvh  = sm;
    float* kvl  = kvh + 128 * 36;
    float* wq_s = kvl + 128 * 36;
    float* xm_s = wq_s + 32 * 136;
    float* q_s  = xm_s + 64 * 36;

    int h = blockIdx.y;
    int tid = threadIdx.x;
    int wid = tid >> 5, lane = tid & 31;
    int lr = lane >> 2, lc = lane & 3;

    for (int i = tid; i < 32 * 128; i += 256) {
        int k = i >> 7, e = i & 127;
        wq_s[k * 136 + e] = to_tf32(wq[k * 128 + e]);
    }
    {
        const float4* hsrc = (const float4*)(kvhg + h * QKDIM * DHEAD);
        const float4* lsrc = (const float4*)(kvlg + h * QKDIM * DHEAD);
        for (int i = tid; i < 1024; i += 256) {
            int e = i >> 3, c4 = (i & 7) * 4;
            float4 hv = hsrc[i], lv = lsrc[i];
            *(float4*)(&kvh[e * 36 + c4]) = hv;
            *(float4*)(&kvl[e * 36 + c4]) = lv;
        }
    }
    float itq = 1.0f / fminf(fmaxf(temp_q[h], 0.1f), 2.0f);

    for (int ch = 0; ch < 2; ch++) {
        int row0 = blockIdx.x * 128 + ch * 64;
        __syncthreads();   // staging / previous chunk complete
        {
            int r = tid >> 2, c0 = (tid & 3) * 8;
            const float* src = xm + (size_t)(row0 + r) * DMODEL + h * DHEAD + c0;
            float4 v1 = *(const float4*)src, v2 = *(const float4*)(src + 4);
            float* dst = &xm_s[r * 36 + c0];
            dst[0] = v1.x; dst[1] = v1.y; dst[2] = v1.z; dst[3] = v1.w;
            dst[4] = v2.x; dst[5] = v2.y; dst[6] = v2.z; dst[7] = v2.w;
        }
        __syncthreads();

        {
            int wm = (wid & 3) * 16, wn = (wid >> 2) * 64;
            float acc[8][4];
#pragma unroll
            for (int i = 0; i < 8; i++)
#pragma unroll
                for (int j = 0; j < 4; j++) acc[i][j] = 0.f;
#pragma unroll
            for (int ks = 0; ks < 32; ks += 8) {
                uint32_t a[4];
                a[0] = __float_as_uint(xm_s[(wm + lr) * 36 + ks + lc]);
                a[1] = __float_as_uint(xm_s[(wm + lr + 8) * 36 + ks + lc]);
                a[2] = __float_as_uint(xm_s[(wm + lr) * 36 + ks + lc + 4]);
                a[3] = __float_as_uint(xm_s[(wm + lr + 8) * 36 + ks + lc + 4]);
#pragma unroll
                for (int nt = 0; nt < 8; nt++) {
                    uint32_t b[2];
                    b[0] = __float_as_uint(wq_s[(ks + lc) * 136 + wn + nt * 8 + lr]);
                    b[1] = __float_as_uint(wq_s[(ks + lc + 4) * 136 + wn + nt * 8 + lr]);
                    mma_tf32(acc[nt], a, b);
                }
            }
#pragma unroll
            for (int nt = 0; nt < 8; nt++) {
                int col = wn + nt * 8 + 2 * lc;
                int r = wm + lr;
                q_s[r * 132 + col]           = acc[nt][0] * itq;
                q_s[r * 132 + col + 1]       = acc[nt][1] * itq;
                q_s[(r + 8) * 132 + col]     = acc[nt][2] * itq;
                q_s[(r + 8) * 132 + col + 1] = acc[nt][3] * itq;
            }
        }
        __syncthreads();
        {
            int r = tid >> 2, sub = tid & 3;
            float* row = q_s + r * 132;
            float mx = -1e30f;
#pragma unroll
            for (int k = 0; k < 32; k++) mx = fmaxf(mx, row[sub + k * 4]);
            mx = fmaxf(mx, __shfl_xor_sync(0xffffffffu, mx, 1));
            mx = fmaxf(mx, __shfl_xor_sync(0xffffffffu, mx, 2));
            float ev[32], sum = 0.f;
#pragma unroll
            for (int k = 0; k < 32; k++) { ev[k] = __expf(row[sub + k * 4] - mx); sum += ev[k]; }
            sum += __shfl_xor_sync(0xffffffffu, sum, 1);
            sum += __shfl_xor_sync(0xffffffffu, sum, 2);
            float inv = 1.0f / sum;
#pragma unroll
            for (int k = 0; k < 32; k++) row[sub + k * 4] = to_tf32(ev[k] * inv);
        }
        __syncthreads();
        {
            int wm = (wid & 3) * 16;
            int part = wid >> 2;
            const float* kvp = part ? kvl : kvh;
            float acc[4][4];
#pragma unroll
            for (int i = 0; i < 4; i++)
#pragma unroll
                for (int j = 0; j < 4; j++) acc[i][j] = 0.f;
#pragma unroll
            for (int ks = 0; ks < 128; ks += 8) {
                uint32_t a[4];
                a[0] = __float_as_uint(q_s[(wm + lr) * 132 + ks + lc]);
                a[1] = __float_as_uint(q_s[(wm + lr + 8) * 132 + ks + lc]);
                a[2] = __float_as_uint(q_s[(wm + lr) * 132 + ks + lc + 4]);
                a[3] = __float_as_uint(q_s[(wm + lr + 8) * 132 + ks + lc + 4]);
#pragma unroll
                for (int nt = 0; nt < 4; nt++) {
                    uint32_t b[2];
                    b[0] = __float_as_uint(kvp[(ks + lc) * 36 + nt * 8 + lr]);
                    b[1] = __float_as_uint(kvp[(ks + lc + 4) * 36 + nt * 8 + lr]);
                    mma_tf32(acc[nt], a, b);
                }
            }
            if (part == 1) {
#pragma unroll
                for (int nt = 0; nt < 4; nt++) {
                    int col = nt * 8 + 2 * lc;
                    int r = wm + lr;
                    xm_s[r * 36 + col]           = acc[nt][0];
                    xm_s[r * 36 + col + 1]       = acc[nt][1];
                    xm_s[(r + 8) * 36 + col]     = acc[nt][2];
                    xm_s[(r + 8) * 36 + col + 1] = acc[nt][3];
                }
            }
            __syncthreads();
            if (part == 0) {
#pragma unroll
                for (int nt = 0; nt < 4; nt++) {
                    int col = nt * 8 + 2 * lc;
#pragma unroll
                    for (int half = 0; half < 2; half++) {
                        int r = wm + lr + half * 8;
                        float v0 = to_tf32(acc[nt][half * 2 + 0] + xm_s[r * 36 + col]);
                        float v1 = to_tf32(acc[nt][half * 2 + 1] + xm_s[r * 36 + col + 1]);
                        float2 o; o.x = v0; o.y = v1;
                        *(float2*)(out + (size_t)(row0 + r) * DMODEL + h * DHEAD + col) = o;
                    }
                }
            }
        }
    }
}

// ---------------- head: out[n] = LN(fx) @ head_w + head_b ----------------
__global__ void head_kernel(const float* __restrict__ fx, const float* __restrict__ g,
                            const float* __restrict__ b, const float* __restrict__ hw,
                            const float* __restrict__ hb, float* __restrict__ out) {
    __shared__ float sh[8];
    int n = blockIdx.x, t = threadIdx.x;
    float v = fx[(size_t)n * DMODEL + t];
    float mean = block_sum256(v, sh) * (1.0f / DMODEL);
    float d = v - mean;
    float var = block_sum256(d * d, sh) * (1.0f / DMODEL);
    float rstd = rsqrtf(var + 1e-5f);
    float hn = d * rstd * g[t] + b[t];
    float dot = block_sum256(hn * hw[t], sh);
    if (t == 0) out[n] = dot + hb[0];
}

// ---------------- launch ----------------
extern "C" void kernel_launch(void* const* d_in, const int* in_sizes, int n_in,
                              void* d_out, int out_size) {
    const float* x          = (const float*)d_in[0];
    const float* pre_w1     = (const float*)d_in[1];
    const float* pre_b1     = (const float*)d_in[2];
    const float* pre_w2     = (const float*)d_in[3];
    const float* pre_b2     = (const float*)d_in[4];
    const float* placeholder= (const float*)d_in[5];
    const float* ln1_g      = (const float*)d_in[6];
    const float* ln1_b      = (const float*)d_in[7];
    const float* inp_w      = (const float*)d_in[8];
    const float* inp_b      = (const float*)d_in[9];
    const float* temp_q     = (const float*)d_in[10];
    const float* temp_k     = (const float*)d_in[11];
    const float* wq         = (const float*)d_in[12];
    const float* wk         = (const float*)d_in[13];
    const float* wv         = (const float*)d_in[14];
    const float* out_w1     = (const float*)d_in[15];
    const float* out_b1     = (const float*)d_in[16];
    const float* out_w2     = (const float*)d_in[17];
    const float* out_b2     = (const float*)d_in[18];
    const float* ln2_g      = (const float*)d_in[19];
    const float* ln2_b      = (const float*)d_in[20];
    const float* mlp_w1     = (const float*)d_in[21];
    const float* mlp_b1     = (const float*)d_in[22];
    const float* mlp_w2     = (const float*)d_in[23];
    const float* mlp_b2     = (const float*)d_in[24];
    const float* ln3_g      = (const float*)d_in[25];
    const float* ln3_b      = (const float*)d_in[26];
    const float* head_w     = (const float*)d_in[27];
    const float* head_b     = (const float*)d_in[28];

    float *fx, *t1, *t2, *t3, *hidden, *kvp, *kvh, *kvl, *wc;
    cudaGetSymbolAddress((void**)&fx, g_fx);
    cudaGetSymbolAddress((void**)&t1, g_t1);
    cudaGetSymbolAddress((void**)&t2, g_t2);
    cudaGetSymbolAddress((void**)&t3, g_t3);
    cudaGetSymbolAddress((void**)&hidden, g_hidden);
    cudaGetSymbolAddress((void**)&kvp, g_kvp);
    cudaGetSymbolAddress((void**)&kvh, g_kvh);
    cudaGetSymbolAddress((void**)&kvl, g_kvl);
    cudaGetSymbolAddress((void**)&wc, g_wc);

    float* iwc   = wc;
    float* ow1c  = wc + 1 * WCONV_PER;
    float* ow2c  = wc + 2 * WCONV_PER;
    float* mw1c  = wc + 3 * WCONV_PER;
    float* mw2c  = wc + 4 * WCONV_PER;
    float* pw2c  = wc + 5 * WCONV_PER;

    const int gemm_smem = GEMM_SMEM_FLOATS * 4;
    const int kv_smem = KV_SMEM_FLOATS * 4;
    const int qkv_smem = QKV_SMEM_FLOATS * 4;
    cudaFuncSetAttribute(gemm_kernel, cudaFuncAttributeMaxDynamicSharedMemorySize, gemm_smem);
    cudaFuncSetAttribute(kv_mma_kernel, cudaFuncAttributeMaxDynamicSharedMemorySize, kv_smem);
    cudaFuncSetAttribute(qkv_mma_kernel, cudaFuncAttributeMaxDynamicSharedMemorySize, qkv_smem);

    dim3 ggrid(NPTS / TBM, DMODEL / TBN);

    conv5_tf32_kernel<<<dim3((WCONV_PER / 4 + 255) / 256, 5), 256>>>(inp_w, out_w1, out_w2,
                                                                     mlp_w1, mlp_w2, wc);
    conv_tf32_kernel<<<(131072 / 4 + 255) / 256, 256>>>(pre_w2, pw2c, 131072 / 4);

    pre1_kernel<<<NPTS * 512 / 256, 256>>>(x, pre_w1, pre_b1, hidden);
    gemm_kernel<<<ggrid, 256, gemm_smem>>>(hidden, 512, pw2c, pre_b2, placeholder, nullptr, fx, 0, 0);

    for (int i = 0; i < NLAYERS; i++) {
        const float* iw  = iwc  + (size_t)i * 65536;
        const float* ow1 = ow1c + (size_t)i * 65536;
        const float* ow2 = ow2c + (size_t)i * 65536;
        const float* mw1 = mw1c + (size_t)i * 65536;
        const float* mw2 = mw2c + (size_t)i * 65536;

        ln_kernel<<<NPTS / 8, 256>>>(fx, ln1_g + i * 256, ln1_b + i * 256, t1);
        gemm_kernel<<<ggrid, 256, gemm_smem>>>(t1, 256, iw, inp_b + i * 256, nullptr, nullptr, t2, 0, 1);
        kv_mma_kernel<<<dim3(KVBLK, NH), 256, kv_smem>>>(t2, wk + (size_t)i * 4096,
                                                         wv + (size_t)i * 1024, temp_k + i * NH, kvp);
        kvn_kernel<<<(NH * QKDIM * DHEAD + 255) / 256, 256>>>(kvp, kvh, kvl);
        qkv_mma_kernel<<<dim3(NPTS / 128, NH), 256, qkv_smem>>>(t2, wq + (size_t)i * 4096,
                                                                temp_q + i * NH, kvh, kvl, t3);
        gemm_kernel<<<ggrid, 256, gemm_smem>>>(t3, 256, ow1, out_b1 + i * 256, nullptr, nullptr, t1, 1, 1);
        gemm_kernel<<<ggrid, 256, gemm_smem>>>(t1, 256, ow2, out_b2 + i * 256, nullptr, fx, fx, 0, 0);
        ln_kernel<<<NPTS / 8, 256>>>(fx, ln2_g + i * 256, ln2_b + i * 256, t1);
        gemm_kernel<<<ggrid, 256, gemm_smem>>>(t1, 256, mw1, mlp_b1 + i * 256, nullptr, nullptr, t2, 1, 1);
        gemm_kernel<<<ggrid, 256, gemm_smem>>>(t2, 256, mw2, mlp_b2 + i * 256, nullptr, fx, fx, 0, 0);
    }
    head_kernel<<<NPTS, 256>>>(fx, ln3_g, ln3_b, head_w, head_b, (float*)d_out);
}

// round 10
// speedup vs baseline: 1.0739x; 1.0098x over previous
#include <cuda_runtime.h>
#include <math.h>
#include <stdint.h>

#define NPTS 32768
#define DMODEL 256
#define NH 8
#define DHEAD 32
#define QKDIM 128
#define NLAYERS 5
#define KVBLK 32

// ---------------- static device scratch (no allocs allowed) ----------------
__device__ float g_fx[NPTS * DMODEL];
__device__ float g_t1[NPTS * DMODEL];
__device__ float g_t2[NPTS * DMODEL];
__device__ float g_t3[NPTS * DMODEL];
__device__ float g_hidden[NPTS * 512];
__device__ float g_kvp[KVBLK * NH * QKDIM * 40];  // per-block partials, col 32 = S
__device__ float g_kvh[NH * QKDIM * DHEAD];
__device__ float g_kvl[NH * QKDIM * DHEAD];
#define WCONV_PER 327680
__device__ float g_wc[5 * WCONV_PER + 131072];

__device__ __forceinline__ float gelu_f(float x) {
    return 0.5f * x * (1.0f + erff(x * 0.70710678118654752f));
}

__device__ __forceinline__ float to_tf32(float x) {
    uint32_t u;
    asm("cvt.rna.tf32.f32 %0, %1;" : "=r"(u) : "f"(x));
    return __uint_as_float(u);
}

__device__ __forceinline__ void mma_tf32(float* c, const uint32_t* a, const uint32_t* b) {
    asm volatile(
        "mma.sync.aligned.m16n8k8.row.col.f32.tf32.tf32.f32 "
        "{%0,%1,%2,%3}, {%4,%5,%6,%7}, {%8,%9}, {%0,%1,%2,%3};\n"
        : "+f"(c[0]), "+f"(c[1]), "+f"(c[2]), "+f"(c[3])
        : "r"(a[0]), "r"(a[1]), "r"(a[2]), "r"(a[3]), "r"(b[0]), "r"(b[1]));
}

__device__ __forceinline__ void cpa16(float* dst, const float* src) {
    uint32_t d = (uint32_t)__cvta_generic_to_shared(dst);
    asm volatile("cp.async.cg.shared.global [%0], [%1], 16;\n" :: "r"(d), "l"(src));
}

// ---------------- tf32 weight conversion: 5 equal tensors in one launch ----------------
__global__ void conv5_tf32_kernel(const float* __restrict__ s0, const float* __restrict__ s1,
                                  const float* __restrict__ s2, const float* __restrict__ s3,
                                  const float* __restrict__ s4, float* __restrict__ dst) {
    const float* srcs[5] = {s0, s1, s2, s3, s4};
    int which = blockIdx.y;
    int i = blockIdx.x * 256 + threadIdx.x;
    if (i < WCONV_PER / 4) {
        float4 v = ((const float4*)srcs[which])[i];
        v.x = to_tf32(v.x); v.y = to_tf32(v.y);
        v.z = to_tf32(v.z); v.w = to_tf32(v.w);
        ((float4*)(dst + (size_t)which * WCONV_PER))[i] = v;
    }
}

__global__ void conv_tf32_kernel(const float* __restrict__ src, float* __restrict__ dst, int n4) {
    int i = blockIdx.x * 256 + threadIdx.x;
    if (i < n4) {
        float4 v = ((const float4*)src)[i];
        v.x = to_tf32(v.x); v.y = to_tf32(v.y);
        v.z = to_tf32(v.z); v.w = to_tf32(v.w);
        ((float4*)dst)[i] = v;
    }
}

// ---------------- preprocess: hidden = tf32(gelu(x @ pre_w1 + b1)) ----------------
__global__ void pre1_kernel(const float* __restrict__ x, const float* __restrict__ w1,
                            const float* __restrict__ b1, float* __restrict__ hidden) {
    int idx = blockIdx.x * 256 + threadIdx.x;
    int n = idx >> 9, j = idx & 511;
    float x0 = x[n * 3 + 0], x1 = x[n * 3 + 1], x2 = x[n * 3 + 2];
    float a = x0 * w1[j] + x1 * w1[512 + j] + x2 * w1[1024 + j] + b1[j];
    hidden[idx] = to_tf32(gelu_f(a));
}

// ---------------- tf32 tensor-core GEMM, 3-stage cp.async pipeline ----------------
#define TBM 128
#define TBN 128
#define TBK 32
#define AS_STRIDE 36
#define BS_STRIDE 136
#define AS_FLOATS (TBM * AS_STRIDE)
#define BS_FLOATS (TBK * BS_STRIDE)
#define NSTAGE 3
#define GEMM_SMEM_FLOATS (NSTAGE * (AS_FLOATS + BS_FLOATS))
__global__ __launch_bounds__(256, 2)
void gemm_kernel(const float* __restrict__ A, int K,
                 const float* __restrict__ W,
                 const float* __restrict__ bias,
                 const float* __restrict__ colbias,
                 const float* __restrict__ residual,
                 float* __restrict__ Y, int act, int rnd) {
    extern __shared__ float smem[];
    float* As = smem;
    float* Bs = smem + NSTAGE * AS_FLOATS;

    int m0 = blockIdx.x * TBM;
    int n0 = blockIdx.y * TBN;
    int tid = threadIdx.x;
    int wid = tid >> 5, lane = tid & 31;
    int wm = (wid >> 2) * 64;
    int wn = (wid & 3) * 32;
    int lr = lane >> 2;
    int lc = lane & 3;

    float acc[4][4][4];
#pragma unroll
    for (int i = 0; i < 4; i++)
#pragma unroll
        for (int j = 0; j < 4; j++)
#pragma unroll
            for (int k = 0; k < 4; k++) acc[i][j][k] = 0.f;

    int a_r = tid >> 3;
    int a_kc = (tid & 7) * 4;
    int b_kr = tid >> 5;
    int b_nc = lane * 4;

    int nit = K / TBK;

    // prologue: prefetch stages 0, 1
#pragma unroll
    for (int pf = 0; pf < 2; pf++) {
        float* as = As + pf * AS_FLOATS;
        float* bs = Bs + pf * BS_FLOATS;
        int k0 = pf * TBK;
#pragma unroll
        for (int rr = 0; rr < 4; rr++) {
            int row = a_r + rr * 32;
            cpa16(&as[row * AS_STRIDE + a_kc], A + (size_t)(m0 + row) * K + k0 + a_kc);
        }
#pragma unroll
        for (int kk = 0; kk < 4; kk++) {
            int krow = b_kr + kk * 8;
            cpa16(&bs[krow * BS_STRIDE + b_nc], W + (size_t)(k0 + krow) * DMODEL + n0 + b_nc);
        }
        asm volatile("cp.async.commit_group;\n");
    }

    for (int it = 0; it < nit; it++) {
        int cur = it % NSTAGE;
        if (it + 2 < nit) {
            int nxt = (it + 2) % NSTAGE;
            int k0 = (it + 2) * TBK;
            float* as = As + nxt * AS_FLOATS;
            float* bs = Bs + nxt * BS_FLOATS;
#pragma unroll
            for (int rr = 0; rr < 4; rr++) {
                int row = a_r + rr * 32;
                cpa16(&as[row * AS_STRIDE + a_kc], A + (size_t)(m0 + row) * K + k0 + a_kc);
            }
#pragma unroll
            for (int kk = 0; kk < 4; kk++) {
                int krow = b_kr + kk * 8;
                cpa16(&bs[krow * BS_STRIDE + b_nc], W + (size_t)(k0 + krow) * DMODEL + n0 + b_nc);
            }
            asm volatile("cp.async.commit_group;\n");
        }
        // groups newer than stage `it`: min(nit-1, it+2) - it
        int newer = nit - 1 - it;
        if (newer >= 2)       asm volatile("cp.async.wait_group 2;\n");
        else if (newer == 1)  asm volatile("cp.async.wait_group 1;\n");
        else                  asm volatile("cp.async.wait_group 0;\n");
        __syncthreads();

        const float* as = As + cur * AS_FLOATS;
        const float* bs = Bs + cur * BS_FLOATS;
#pragma unroll
        for (int ks = 0; ks < TBK; ks += 8) {
            uint32_t af[4][4], bf[4][2];
#pragma unroll
            for (int mt = 0; mt < 4; mt++) {
                int r = wm + mt * 16 + lr;
                int c = ks + lc;
                af[mt][0] = __float_as_uint(as[r * AS_STRIDE + c]);
                af[mt][1] = __float_as_uint(as[(r + 8) * AS_STRIDE + c]);
                af[mt][2] = __float_as_uint(as[r * AS_STRIDE + c + 4]);
                af[mt][3] = __float_as_uint(as[(r + 8) * AS_STRIDE + c + 4]);
            }
#pragma unroll
            for (int nt = 0; nt < 4; nt++) {
                int n = wn + nt * 8 + lr;
                int c = ks + lc;
                bf[nt][0] = __float_as_uint(bs[c * BS_STRIDE + n]);
                bf[nt][1] = __float_as_uint(bs[(c + 4) * BS_STRIDE + n]);
            }
#pragma unroll
            for (int mt = 0; mt < 4; mt++)
#pragma unroll
                for (int nt = 0; nt < 4; nt++)
                    mma_tf32(acc[mt][nt], af[mt], bf[nt]);
        }
        __syncthreads();
    }

#pragma unroll
    for (int mt = 0; mt < 4; mt++) {
        int row = m0 + wm + mt * 16 + lr;
#pragma unroll
        for (int nt = 0; nt < 4; nt++) {
            int col = n0 + wn + nt * 8 + lc * 2;
#pragma unroll
            for (int half = 0; half < 2; half++) {
                int r = row + half * 8;
                float v0 = acc[mt][nt][half * 2 + 0];
                float v1 = acc[mt][nt][half * 2 + 1];
                if (bias)    { v0 += bias[col];        v1 += bias[col + 1]; }
                if (colbias) { v0 += colbias[col];     v1 += colbias[col + 1]; }
                if (act)     { v0 = gelu_f(v0);        v1 = gelu_f(v1); }
                if (residual) {
                    v0 += residual[(size_t)r * DMODEL + col];
                    v1 += residual[(size_t)r * DMODEL + col + 1];
                }
                if (rnd)     { v0 = to_tf32(v0);       v1 = to_tf32(v1); }
                float2 o; o.x = v0; o.y = v1;
                *(float2*)(Y + (size_t)r * DMODEL + col) = o;
            }
        }
    }
}

// ---------------- LayerNorm: warp per row, single pass, tf32-rounded output ----------------
__global__ void ln_kernel(const float* __restrict__ X, const float* __restrict__ g,
                          const float* __restrict__ b, float* __restrict__ Y) {
    int wid = threadIdx.x >> 5, lane = threadIdx.x & 31;
    int row = blockIdx.x * 8 + wid;
    const float4* X4 = (const float4*)(X + (size_t)row * DMODEL);
    const float4* G4 = (const float4*)g;
    const float4* B4 = (const float4*)b;
    float4* Y4 = (float4*)(Y + (size_t)row * DMODEL);

    float4 a = X4[lane];
    float4 c = X4[lane + 32];
    float s = a.x + a.y + a.z + a.w + c.x + c.y + c.z + c.w;
    float q = a.x * a.x + a.y * a.y + a.z * a.z + a.w * a.w
            + c.x * c.x + c.y * c.y + c.z * c.z + c.w * c.w;
#pragma unroll
    for (int o = 16; o > 0; o >>= 1) {
        s += __shfl_xor_sync(0xffffffffu, s, o);
        q += __shfl_xor_sync(0xffffffffu, q, o);
    }
    float mean = s * (1.0f / DMODEL);
    float var = q * (1.0f / DMODEL) - mean * mean;
    float rstd = rsqrtf(fmaxf(var, 0.f) + 1e-5f);

    float4 g1 = G4[lane], g2 = G4[lane + 32];
    float4 b1 = B4[lane], b2 = B4[lane + 32];
    float4 o1, o2;
    o1.x = to_tf32((a.x - mean) * rstd * g1.x + b1.x);
    o1.y = to_tf32((a.y - mean) * rstd * g1.y + b1.y);
    o1.z = to_tf32((a.z - mean) * rstd * g1.z + b1.z);
    o1.w = to_tf32((a.w - mean) * rstd * g1.w + b1.w);
    o2.x = to_tf32((c.x - mean) * rstd * g2.x + b2.x);
    o2.y = to_tf32((c.y - mean) * rstd * g2.y + b2.y);
    o2.z = to_tf32((c.z - mean) * rstd * g2.z + b2.z);
    o2.w = to_tf32((c.w - mean) * rstd * g2.w + b2.w);
    Y4[lane] = o1;
    Y4[lane + 32] = o2;
}

// ---------------- kvn: reduce 32 partials, normalize by S, split hi/lo ----------------
__global__ void kvn_kernel(const float* __restrict__ kvp, float* __restrict__ kvh,
                           float* __restrict__ kvl) {
    int idx = blockIdx.x * 256 + threadIdx.x;  // NH*QKDIM*DHEAD = 32768
    int he = idx >> 5, c = idx & 31;
    float sv = 0.f, ss = 0.f;
    const float* base = kvp + (size_t)he * 40;
#pragma unroll 4
    for (int b = 0; b < KVBLK; b++) {
        const float* p = base + (size_t)b * NH * QKDIM * 40;
        sv += p[c];
        ss += p[32];
    }
    float v = sv / ss;
    float hi = to_tf32(v);
    kvh[idx] = hi;
    kvl[idx] = to_tf32(v - hi);
}

// ================= tensor-core KV =================
// grid (32, NH), 1024 rows/block in 16 chunks of 64; partials out (no atomics)
#define KV_SMEM_FLOATS (32*136 + 32*44 + 64*36 + 128*68 + 64*44)
__global__ void kv_mma_kernel(const float* __restrict__ xm, const float* __restrict__ wk,
                              const float* __restrict__ wv, const float* __restrict__ temp_k,
                              float* __restrict__ kvp) {
    extern __shared__ float sm[];
    float* wk_s = sm;
    float* wv_s = wk_s + 32 * 136;
    float* xm_s = wv_s + 32 * 44;
    float* kT_s = xm_s + 64 * 36;
    float* v_s  = kT_s + 128 * 68;

    int h = blockIdx.y;
    int tid = threadIdx.x;
    int wid = tid >> 5, lane = tid & 31;
    int lr = lane >> 2, lc = lane & 3;

    for (int i = tid; i < 32 * 128; i += 256) {
        int k = i >> 7, e = i & 127;
        wk_s[k * 136 + e] = to_tf32(wk[k * 128 + e]);
    }
    for (int i = tid; i < 32 * 32; i += 256) {
        int k = i >> 5, c = i & 31;
        wv_s[k * 44 + c] = to_tf32(wv[k * 32 + c]);
    }
    float itk = 1.0f / fminf(fmaxf(temp_k[h], 0.1f), 2.0f);

    float kvacc[5][4];
#pragma unroll
    for (int i = 0; i < 5; i++)
#pragma unroll
        for (int j = 0; j < 4; j++) kvacc[i][j] = 0.f;

    int row0 = blockIdx.x * 1024;

    for (int ch = 0; ch < 16; ch++) {
        __syncthreads();
        {
            int r = tid >> 2, c0 = (tid & 3) * 8;
            const float* src = xm + (size_t)(row0 + ch * 64 + r) * DMODEL + h * DHEAD + c0;
            float4 v1 = *(const float4*)src, v2 = *(const float4*)(src + 4);
            float* dst = &xm_s[r * 36 + c0];
            dst[0] = v1.x; dst[1] = v1.y; dst[2] = v1.z; dst[3] = v1.w;
            dst[4] = v2.x; dst[5] = v2.y; dst[6] = v2.z; dst[7] = v2.w;
        }
        __syncthreads();

        {
            int wm = (wid & 3) * 16, wn = (wid >> 2) * 64;
            float acc[8][4];
#pragma unroll
            for (int i = 0; i < 8; i++)
#pragma unroll
                for (int j = 0; j < 4; j++) acc[i][j] = 0.f;
#pragma unroll
            for (int ks = 0; ks < 32; ks += 8) {
                uint32_t a[4];
                a[0] = __float_as_uint(xm_s[(wm + lr) * 36 + ks + lc]);
                a[1] = __float_as_uint(xm_s[(wm + lr + 8) * 36 + ks + lc]);
                a[2] = __float_as_uint(xm_s[(wm + lr) * 36 + ks + lc + 4]);
                a[3] = __float_as_uint(xm_s[(wm + lr + 8) * 36 + ks + lc + 4]);
#pragma unroll
                for (int nt = 0; nt < 8; nt++) {
                    uint32_t b[2];
                    b[0] = __float_as_uint(wk_s[(ks + lc) * 136 + wn + nt * 8 + lr]);
                    b[1] = __float_as_uint(wk_s[(ks + lc + 4) * 136 + wn + nt * 8 + lr]);
                    mma_tf32(acc[nt], a, b);
                }
            }
#pragma unroll
            for (int nt = 0; nt < 8; nt++) {
                int col = wn + nt * 8 + 2 * lc;
                int r = wm + lr;
                kT_s[col * 68 + r]           = to_tf32(__expf(acc[nt][0] * itk));
                kT_s[(col + 1) * 68 + r]     = to_tf32(__expf(acc[nt][1] * itk));
                kT_s[col * 68 + r + 8]       = to_tf32(__expf(acc[nt][2] * itk));
                kT_s[(col + 1) * 68 + r + 8] = to_tf32(__expf(acc[nt][3] * itk));
            }
        }
        if (wid < 4) {
            int wm = wid * 16;
            float acc[4][4];
#pragma unroll
            for (int i = 0; i < 4; i++)
#pragma unroll
                for (int j = 0; j < 4; j++) acc[i][j] = 0.f;
#pragma unroll
            for (int ks = 0; ks < 32; ks += 8) {
                uint32_t a[4];
                a[0] = __float_as_uint(xm_s[(wm + lr) * 36 + ks + lc]);
                a[1] = __float_as_uint(xm_s[(wm + lr + 8) * 36 + ks + lc]);
                a[2] = __float_as_uint(xm_s[(wm + lr) * 36 + ks + lc + 4]);
                a[3] = __float_as_uint(xm_s[(wm + lr + 8) * 36 + ks + lc + 4]);
#pragma unroll
                for (int nt = 0; nt < 4; nt++) {
                    uint32_t b[2];
                    b[0] = __float_as_uint(wv_s[(ks + lc) * 44 + nt * 8 + lr]);
                    b[1] = __float_as_uint(wv_s[(ks + lc + 4) * 44 + nt * 8 + lr]);
                    mma_tf32(acc[nt], a, b);
                }
            }
#pragma unroll
            for (int nt = 0; nt < 4; nt++) {
                int col = nt * 8 + 2 * lc;
                int r = wm + lr;
                v_s[r * 44 + col]           = to_tf32(acc[nt][0]);
                v_s[r * 44 + col + 1]       = to_tf32(acc[nt][1]);
                v_s[(r + 8) * 44 + col]     = to_tf32(acc[nt][2]);
                v_s[(r + 8) * 44 + col + 1] = to_tf32(acc[nt][3]);
            }
        }
        if (tid < 64) v_s[tid * 44 + 32] = 1.0f;
        __syncthreads();

        {
            int we = wid * 16;
#pragma unroll
            for (int ks = 0; ks < 64; ks += 8) {
                uint32_t a[4];
                a[0] = __float_as_uint(kT_s[(we + lr) * 68 + ks + lc]);
                a[1] = __float_as_uint(kT_s[(we + lr + 8) * 68 + ks + lc]);
                a[2] = __float_as_uint(kT_s[(we + lr) * 68 + ks + lc + 4]);
                a[3] = __float_as_uint(kT_s[(we + lr + 8) * 68 + ks + lc + 4]);
#pragma unroll
                for (int nt = 0; nt < 5; nt++) {
                    uint32_t b[2];
                    b[0] = __float_as_uint(v_s[(ks + lc) * 44 + nt * 8 + lr]);
                    b[1] = __float_as_uint(v_s[(ks + lc + 4) * 44 + nt * 8 + lr]);
                    mma_tf32(kvacc[nt], a, b);
                }
            }
        }
    }
    {   // flush partials (no atomics)
        float* dst = kvp + (size_t)(blockIdx.x * NH + h) * QKDIM * 40;
        int we = wid * 16;
#pragma unroll
        for (int nt = 0; nt < 5; nt++) {
            int col = nt * 8 + 2 * lc;
            int e0 = we + lr, e1 = we + lr + 8;
            if (col <= 32) {
                dst[e0 * 40 + col] = kvacc[nt][0];
                dst[e1 * 40 + col] = kvacc[nt][2];
            }
            if (col + 1 <= 32) {
                dst[e0 * 40 + col + 1] = kvacc[nt][1];
                dst[e1 * 40 + col + 1] = kvacc[nt][3];
            }
        }
    }
}

// ================= tensor-core QKV: 256 rows/block in 4 chunks =================
#define QKV_SMEM_FLOATS (128*36*2 + 32*136 + 64*36 + 64*132)
__global__ void qkv_mma_kernel(const float* __restrict__ xm, const float* __restrict__ wq,
                               const float* __restrict__ temp_q,
                               const float* __restrict__ kvhg, const float* __restrict__ kvlg,
                               float* __restrict__ out) {
    extern __shared__ float sm[];
    float* kvh  = sm;
    float* kvl  = kvh + 128 * 36;
    float* wq_s = kvl + 128 * 36;
    float* xm_s = wq_s + 32 * 136;
    float* q_s  = xm_s + 64 * 36;

    int h = blockIdx.y;
    int tid = threadIdx.x;
    int wid = tid >> 5, lane = tid & 31;
    int lr = lane >> 2, lc = lane & 3;

    for (int i = tid; i < 32 * 128; i += 256) {
        int k = i >> 7, e = i & 127;
        wq_s[k * 136 + e] = to_tf32(wq[k * 128 + e]);
    }
    {
        const float4* hsrc = (const float4*)(kvhg + h * QKDIM * DHEAD);
        const float4* lsrc = (const float4*)(kvlg + h * QKDIM * DHEAD);
        for (int i = tid; i < 1024; i += 256) {
            int e = i >> 3, c4 = (i & 7) * 4;
            float4 hv = hsrc[i], lv = lsrc[i];
            *(float4*)(&kvh[e * 36 + c4]) = hv;
            *(float4*)(&kvl[e * 36 + c4]) = lv;
        }
    }
    float itq = 1.0f / fminf(fmaxf(temp_q[h], 0.1f), 2.0f);

    for (int ch = 0; ch < 4; ch++) {
        int row0 = blockIdx.x * 256 + ch * 64;
        __syncthreads();
        {
            int r = tid >> 2, c0 = (tid & 3) * 8;
            const float* src = xm + (size_t)(row0 + r) * DMODEL + h * DHEAD + c0;
            float4 v1 = *(const float4*)src, v2 = *(const float4*)(src + 4);
            float* dst = &xm_s[r * 36 + c0];
            dst[0] = v1.x; dst[1] = v1.y; dst[2] = v1.z; dst[3] = v1.w;
            dst[4] = v2.x; dst[5] = v2.y; dst[6] = v2.z; dst[7] = v2.w;
        }
        __syncthreads();

        {
            int wm = (wid & 3) * 16, wn = (wid >> 2) * 64;
            float acc[8][4];
#pragma unroll
            for (int i = 0; i < 8; i++)
#pragma unroll
                for (int j = 0; j < 4; j++) acc[i][j] = 0.f;
#pragma unroll
            for (int ks = 0; ks < 32; ks += 8) {
                uint32_t a[4];
                a[0] = __float_as_uint(xm_s[(wm + lr) * 36 + ks + lc]);
                a[1] = __float_as_uint(xm_s[(wm + lr + 8) * 36 + ks + lc]);
                a[2] = __float_as_uint(xm_s[(wm + lr) * 36 + ks + lc + 4]);
                a[3] = __float_as_uint(xm_s[(wm + lr + 8) * 36 + ks + lc + 4]);
#pragma unroll
                for (int nt = 0; nt < 8; nt++) {
                    uint32_t b[2];
                    b[0] = __float_as_uint(wq_s[(ks + lc) * 136 + wn + nt * 8 + lr]);
                    b[1] = __float_as_uint(wq_s[(ks + lc + 4) * 136 + wn + nt * 8 + lr]);
                    mma_tf32(acc[nt], a, b);
                }
            }
#pragma unroll
            for (int nt = 0; nt < 8; nt++) {
                int col = wn + nt * 8 + 2 * lc;
                int r = wm + lr;
                q_s[r * 132 + col]           = acc[nt][0] * itq;
                q_s[r * 132 + col + 1]       = acc[nt][1] * itq;
                q_s[(r + 8) * 132 + col]     = acc[nt][2] * itq;
                q_s[(r + 8) * 132 + col + 1] = acc[nt][3] * itq;
            }
        }
        __syncthreads();
        {
            int r = tid >> 2, sub = tid & 3;
            float* row = q_s + r * 132;
            float mx = -1e30f;
#pragma unroll
            for (int k = 0; k < 32; k++) mx = fmaxf(mx, row[sub + k * 4]);
            mx = fmaxf(mx, __shfl_xor_sync(0xffffffffu, mx, 1));
            mx = fmaxf(mx, __shfl_xor_sync(0xffffffffu, mx, 2));
            float ev[32], sum = 0.f;
#pragma unroll
            for (int k = 0; k < 32; k++) { ev[k] = __expf(row[sub + k * 4] - mx); sum += ev[k]; }
            sum += __shfl_xor_sync(0xffffffffu, sum, 1);
            sum += __shfl_xor_sync(0xffffffffu, sum, 2);
            float inv = 1.0f / sum;
#pragma unroll
            for (int k = 0; k < 32; k++) row[sub + k * 4] = to_tf32(ev[k] * inv);
        }
        __syncthreads();
        {
            int wm = (wid & 3) * 16;
            int part = wid >> 2;
            const float* kvp = part ? kvl : kvh;
            float acc[4][4];
#pragma unroll
            for (int i = 0; i < 4; i++)
#pragma unroll
                for (int j = 0; j < 4; j++) acc[i][j] = 0.f;
#pragma unroll
            for (int ks = 0; ks < 128; ks += 8) {
                uint32_t a[4];
                a[0] = __float_as_uint(q_s[(wm + lr) * 132 + ks + lc]);
                a[1] = __float_as_uint(q_s[(wm + lr + 8) * 132 + ks + lc]);
                a[2] = __float_as_uint(q_s[(wm + lr) * 132 + ks + lc + 4]);
                a[3] = __float_as_uint(q_s[(wm + lr + 8) * 132 + ks + lc + 4]);
#pragma unroll
                for (int nt = 0; nt < 4; nt++) {
                    uint32_t b[2];
                    b[0] = __float_as_uint(kvp[(ks + lc) * 36 + nt * 8 + lr]);
                    b[1] = __float_as_uint(kvp[(ks + lc + 4) * 36 + nt * 8 + lr]);
                    mma_tf32(acc[nt], a, b);
                }
            }
            if (part == 1) {
#pragma unroll
                for (int nt = 0; nt < 4; nt++) {
                    int col = nt * 8 + 2 * lc;
                    int r = wm + lr;
                    xm_s[r * 36 + col]           = acc[nt][0];
                    xm_s[r * 36 + col + 1]       = acc[nt][1];
                    xm_s[(r + 8) * 36 + col]     = acc[nt][2];
                    xm_s[(r + 8) * 36 + col + 1] = acc[nt][3];
                }
            }
            __syncthreads();
            if (part == 0) {
#pragma unroll
                for (int nt = 0; nt < 4; nt++) {
                    int col = nt * 8 + 2 * lc;
#pragma unroll
                    for (int half = 0; half < 2; half++) {
                        int r = wm + lr + half * 8;
                        float v0 = to_tf32(acc[nt][half * 2 + 0] + xm_s[r * 36 + col]);
                        float v1 = to_tf32(acc[nt][half * 2 + 1] + xm_s[r * 36 + col + 1]);
                        float2 o; o.x = v0; o.y = v1;
                        *(float2*)(out + (size_t)(row0 + r) * DMODEL + h * DHEAD + col) = o;
                    }
                }
            }
        }
    }
}

// ---------------- head: warp per row ----------------
__global__ void head_kernel(const float* __restrict__ fx, const float* __restrict__ g,
                            const float* __restrict__ b, const float* __restrict__ hw,
                            const float* __restrict__ hb, float* __restrict__ out) {
    int wid = threadIdx.x >> 5, lane = threadIdx.x & 31;
    int row = blockIdx.x * 8 + wid;
    const float4* X4 = (const float4*)(fx + (size_t)row * DMODEL);
    const float4* G4 = (const float4*)g;
    const float4* B4 = (const float4*)b;
    const float4* H4 = (const float4*)hw;

    float4 a = X4[lane];
    float4 c = X4[lane + 32];
    float s = a.x + a.y + a.z + a.w + c.x + c.y + c.z + c.w;
    float q = a.x * a.x + a.y * a.y + a.z * a.z + a.w * a.w
            + c.x * c.x + c.y * c.y + c.z * c.z + c.w * c.w;
#pragma unroll
    for (int o = 16; o > 0; o >>= 1) {
        s += __shfl_xor_sync(0xffffffffu, s, o);
        q += __shfl_xor_sync(0xffffffffu, q, o);
    }
    float mean = s * (1.0f / DMODEL);
    float var = q * (1.0f / DMODEL) - mean * mean;
    float rstd = rsqrtf(fmaxf(var, 0.f) + 1e-5f);

    float4 g1 = G4[lane], g2 = G4[lane + 32];
    float4 b1 = B4[lane], b2 = B4[lane + 32];
    float4 h1 = H4[lane], h2 = H4[lane + 32];
    float dot =
        ((a.x - mean) * rstd * g1.x + b1.x) * h1.x +
        ((a.y - mean) * rstd * g1.y + b1.y) * h1.y +
        ((a.z - mean) * rstd * g1.z + b1.z) * h1.z +
        ((a.w - mean) * rstd * g1.w + b1.w) * h1.w +
        ((c.x - mean) * rstd * g2.x + b2.x) * h2.x +
        ((c.y - mean) * rstd * g2.y + b2.y) * h2.y +
        ((c.z - mean) * rstd * g2.z + b2.z) * h2.z +
        ((c.w - mean) * rstd * g2.w + b2.w) * h2.w;
#pragma unroll
    for (int o = 16; o > 0; o >>= 1) dot += __shfl_xor_sync(0xffffffffu, dot, o);
    if (lane == 0) out[row] = dot + hb[0];
}

// ---------------- launch ----------------
extern "C" void kernel_launch(void* const* d_in, const int* in_sizes, int n_in,
                              void* d_out, int out_size) {
    const float* x          = (const float*)d_in[0];
    const float* pre_w1     = (const float*)d_in[1];
    const float* pre_b1     = (const float*)d_in[2];
    const float* pre_w2     = (const float*)d_in[3];
    const float* pre_b2     = (const float*)d_in[4];
    const float* placeholder= (const float*)d_in[5];
    const float* ln1_g      = (const float*)d_in[6];
    const float* ln1_b      = (const float*)d_in[7];
    const float* inp_w      = (const float*)d_in[8];
    const float* inp_b      = (const float*)d_in[9];
    const float* temp_q     = (const float*)d_in[10];
    const float* temp_k     = (const float*)d_in[11];
    const float* wq         = (const float*)d_in[12];
    const float* wk         = (const float*)d_in[13];
    const float* wv         = (const float*)d_in[14];
    const float* out_w1     = (const float*)d_in[15];
    const float* out_b1     = (const float*)d_in[16];
    const float* out_w2     = (const float*)d_in[17];
    const float* out_b2     = (const float*)d_in[18];
    const float* ln2_g      = (const float*)d_in[19];
    const float* ln2_b      = (const float*)d_in[20];
    const float* mlp_w1     = (const float*)d_in[21];
    const float* mlp_b1     = (const float*)d_in[22];
    const float* mlp_w2     = (const float*)d_in[23];
    const float* mlp_b2     = (const float*)d_in[24];
    const float* ln3_g      = (const float*)d_in[25];
    const float* ln3_b      = (const float*)d_in[26];
    const float* head_w     = (const float*)d_in[27];
    const float* head_b     = (const float*)d_in[28];

    float *fx, *t1, *t2, *t3, *hidden, *kvp, *kvh, *kvl, *wc;
    cudaGetSymbolAddress((void**)&fx, g_fx);
    cudaGetSymbolAddress((void**)&t1, g_t1);
    cudaGetSymbolAddress((void**)&t2, g_t2);
    cudaGetSymbolAddress((void**)&t3, g_t3);
    cudaGetSymbolAddress((void**)&hidden, g_hidden);
    cudaGetSymbolAddress((void**)&kvp, g_kvp);
    cudaGetSymbolAddress((void**)&kvh, g_kvh);
    cudaGetSymbolAddress((void**)&kvl, g_kvl);
    cudaGetSymbolAddress((void**)&wc, g_wc);

    float* iwc   = wc;
    float* ow1c  = wc + 1 * WCONV_PER;
    float* ow2c  = wc + 2 * WCONV_PER;
    float* mw1c  = wc + 3 * WCONV_PER;
    float* mw2c  = wc + 4 * WCONV_PER;
    float* pw2c  = wc + 5 * WCONV_PER;

    const int gemm_smem = GEMM_SMEM_FLOATS * 4;
    const int kv_smem = KV_SMEM_FLOATS * 4;
    const int qkv_smem = QKV_SMEM_FLOATS * 4;
    cudaFuncSetAttribute(gemm_kernel, cudaFuncAttributeMaxDynamicSharedMemorySize, gemm_smem);
    cudaFuncSetAttribute(kv_mma_kernel, cudaFuncAttributeMaxDynamicSharedMemorySize, kv_smem);
    cudaFuncSetAttribute(qkv_mma_kernel, cudaFuncAttributeMaxDynamicSharedMemorySize, qkv_smem);

    dim3 ggrid(NPTS / TBM, DMODEL / TBN);

    conv5_tf32_kernel<<<dim3((WCONV_PER / 4 + 255) / 256, 5), 256>>>(inp_w, out_w1, out_w2,
                                                                     mlp_w1, mlp_w2, wc);
    conv_tf32_kernel<<<(131072 / 4 + 255) / 256, 256>>>(pre_w2, pw2c, 131072 / 4);

    pre1_kernel<<<NPTS * 512 / 256, 256>>>(x, pre_w1, pre_b1, hidden);
    gemm_kernel<<<ggrid, 256, gemm_smem>>>(hidden, 512, pw2c, pre_b2, placeholder, nullptr, fx, 0, 0);

    for (int i = 0; i < NLAYERS; i++) {
        const float* iw  = iwc  + (size_t)i * 65536;
        const float* ow1 = ow1c + (size_t)i * 65536;
        const float* ow2 = ow2c + (size_t)i * 65536;
        const float* mw1 = mw1c + (size_t)i * 65536;
        const float* mw2 = mw2c + (size_t)i * 65536;

        ln_kernel<<<NPTS / 8, 256>>>(fx, ln1_g + i * 256, ln1_b + i * 256, t1);
        gemm_kernel<<<ggrid, 256, gemm_smem>>>(t1, 256, iw, inp_b + i * 256, nullptr, nullptr, t2, 0, 1);
        kv_mma_kernel<<<dim3(KVBLK, NH), 256, kv_smem>>>(t2, wk + (size_t)i * 4096,
                                                         wv + (size_t)i * 1024, temp_k + i * NH, kvp);
        kvn_kernel<<<(NH * QKDIM * DHEAD + 255) / 256, 256>>>(kvp, kvh, kvl);
        qkv_mma_kernel<<<dim3(NPTS / 256, NH), 256, qkv_smem>>>(t2, wq + (size_t)i * 4096,
                                                                temp_q + i * NH, kvh, kvl, t3);
        gemm_kernel<<<ggrid, 256, gemm_smem>>>(t3, 256, ow1, out_b1 + i * 256, nullptr, nullptr, t1, 1, 1);
        gemm_kernel<<<ggrid, 256, gemm_smem>>>(t1, 256, ow2, out_b2 + i * 256, nullptr, fx, fx, 0, 0);
        ln_kernel<<<NPTS / 8, 256>>>(fx, ln2_g + i * 256, ln2_b + i * 256, t1);
        gemm_kernel<<<ggrid, 256, gemm_smem>>>(t1, 256, mw1, mlp_b1 + i * 256, nullptr, nullptr, t2, 1, 1);
        gemm_kernel<<<ggrid, 256, gemm_smem>>>(t2, 256, mw2, mlp_b2 + i * 256, nullptr, fx, fx, 0, 0);
    }
    head_kernel<<<NPTS / 8, 256>>>(fx, ln3_g, ln3_b, head_w, head_b, (float*)d_out);
}

// round 11
// speedup vs baseline: 1.1131x; 1.0365x over previous
#include <cuda_runtime.h>
#include <math.h>
#include <stdint.h>

#define NPTS 32768
#define DMODEL 256
#define NH 8
#define DHEAD 32
#define QKDIM 128
#define NLAYERS 5
#define KVBLK 32

// ---------------- static device scratch (no allocs allowed) ----------------
__device__ float g_fx[NPTS * DMODEL];
__device__ float g_t1[NPTS * DMODEL];
__device__ float g_t2[NPTS * DMODEL];
__device__ float g_t3[NPTS * DMODEL];
__device__ float g_hidden[NPTS * 512];
__device__ float g_kvp[KVBLK * NH * QKDIM * 40];  // per-block partials, col 32 = S
__device__ float g_kvh[NH * QKDIM * DHEAD];
__device__ float g_kvl[NH * QKDIM * DHEAD];
#define WCONV_PER 327680
__device__ float g_wc[5 * WCONV_PER + 131072];

__device__ __forceinline__ float gelu_f(float x) {
    return 0.5f * x * (1.0f + erff(x * 0.70710678118654752f));
}

__device__ __forceinline__ float to_tf32(float x) {
    uint32_t u;
    asm("cvt.rna.tf32.f32 %0, %1;" : "=r"(u) : "f"(x));
    return __uint_as_float(u);
}

__device__ __forceinline__ void mma_tf32(float* c, const uint32_t* a, const uint32_t* b) {
    asm volatile(
        "mma.sync.aligned.m16n8k8.row.col.f32.tf32.tf32.f32 "
        "{%0,%1,%2,%3}, {%4,%5,%6,%7}, {%8,%9}, {%0,%1,%2,%3};\n"
        : "+f"(c[0]), "+f"(c[1]), "+f"(c[2]), "+f"(c[3])
        : "r"(a[0]), "r"(a[1]), "r"(a[2]), "r"(a[3]), "r"(b[0]), "r"(b[1]));
}

__device__ __forceinline__ void cpa16(float* dst, const float* src) {
    uint32_t d = (uint32_t)__cvta_generic_to_shared(dst);
    asm volatile("cp.async.cg.shared.global [%0], [%1], 16;\n" :: "r"(d), "l"(src));
}

// ---------------- tf32 weight conversion: all 6 tensors in one launch ----------------
__global__ void conv6_tf32_kernel(const float* __restrict__ s0, const float* __restrict__ s1,
                                  const float* __restrict__ s2, const float* __restrict__ s3,
                                  const float* __restrict__ s4, const float* __restrict__ s5,
                                  float* __restrict__ dst) {
    const float* srcs[6] = {s0, s1, s2, s3, s4, s5};
    int which = blockIdx.y;
    int n4 = (which < 5) ? (WCONV_PER / 4) : (131072 / 4);
    int i = blockIdx.x * 256 + threadIdx.x;
    if (i < n4) {
        float4 v = ((const float4*)srcs[which])[i];
        v.x = to_tf32(v.x); v.y = to_tf32(v.y);
        v.z = to_tf32(v.z); v.w = to_tf32(v.w);
        ((float4*)(dst + (size_t)which * WCONV_PER))[i] = v;
    }
}

// ---------------- preprocess: hidden = tf32(gelu(x @ pre_w1 + b1)) ----------------
__global__ void pre1_kernel(const float* __restrict__ x, const float* __restrict__ w1,
                            const float* __restrict__ b1, float* __restrict__ hidden) {
    int idx = blockIdx.x * 256 + threadIdx.x;
    int n = idx >> 9, j = idx & 511;
    float x0 = x[n * 3 + 0], x1 = x[n * 3 + 1], x2 = x[n * 3 + 2];
    float a = x0 * w1[j] + x1 * w1[512 + j] + x2 * w1[1024 + j] + b1[j];
    hidden[idx] = to_tf32(gelu_f(a));
}

// ---------------- tf32 tensor-core GEMM, 2-stage cp.async (R9-best) ----------------
#define TBM 128
#define TBN 128
#define TBK 32
#define AS_STRIDE 36
#define BS_STRIDE 136
#define AS_FLOATS (TBM * AS_STRIDE)
#define BS_FLOATS (TBK * BS_STRIDE)
#define GEMM_SMEM_FLOATS (2 * (AS_FLOATS + BS_FLOATS))
__global__ __launch_bounds__(256, 2)
void gemm_kernel(const float* __restrict__ A, int K,
                 const float* __restrict__ W,
                 const float* __restrict__ bias,
                 const float* __restrict__ colbias,
                 const float* __restrict__ residual,
                 float* __restrict__ Y, int act, int rnd) {
    extern __shared__ float smem[];
    float* As = smem;
    float* Bs = smem + 2 * AS_FLOATS;

    int m0 = blockIdx.x * TBM;
    int n0 = blockIdx.y * TBN;
    int tid = threadIdx.x;
    int wid = tid >> 5, lane = tid & 31;
    int wm = (wid >> 2) * 64;
    int wn = (wid & 3) * 32;
    int lr = lane >> 2;
    int lc = lane & 3;

    float acc[4][4][4];
#pragma unroll
    for (int i = 0; i < 4; i++)
#pragma unroll
        for (int j = 0; j < 4; j++)
#pragma unroll
            for (int k = 0; k < 4; k++) acc[i][j][k] = 0.f;

    int a_r = tid >> 3;
    int a_kc = (tid & 7) * 4;
    int b_kr = tid >> 5;
    int b_nc = lane * 4;

    int nit = K / TBK;

    {
        float* as = As;
        float* bs = Bs;
#pragma unroll
        for (int rr = 0; rr < 4; rr++) {
            int row = a_r + rr * 32;
            cpa16(&as[row * AS_STRIDE + a_kc], A + (size_t)(m0 + row) * K + a_kc);
        }
#pragma unroll
        for (int kk = 0; kk < 4; kk++) {
            int krow = b_kr + kk * 8;
            cpa16(&bs[krow * BS_STRIDE + b_nc], W + (size_t)krow * DMODEL + n0 + b_nc);
        }
        asm volatile("cp.async.commit_group;\n");
    }

    for (int it = 0; it < nit; it++) {
        int cur = it & 1;
        if (it + 1 < nit) {
            int nxt = (it + 1) & 1;
            int k0 = (it + 1) * TBK;
            float* as = As + nxt * AS_FLOATS;
            float* bs = Bs + nxt * BS_FLOATS;
#pragma unroll
            for (int rr = 0; rr < 4; rr++) {
                int row = a_r + rr * 32;
                cpa16(&as[row * AS_STRIDE + a_kc], A + (size_t)(m0 + row) * K + k0 + a_kc);
            }
#pragma unroll
            for (int kk = 0; kk < 4; kk++) {
                int krow = b_kr + kk * 8;
                cpa16(&bs[krow * BS_STRIDE + b_nc], W + (size_t)(k0 + krow) * DMODEL + n0 + b_nc);
            }
            asm volatile("cp.async.commit_group;\n");
            asm volatile("cp.async.wait_group 1;\n");
        } else {
            asm volatile("cp.async.wait_group 0;\n");
        }
        __syncthreads();

        const float* as = As + cur * AS_FLOATS;
        const float* bs = Bs + cur * BS_FLOATS;
#pragma unroll
        for (int ks = 0; ks < TBK; ks += 8) {
            uint32_t af[4][4], bf[4][2];
#pragma unroll
            for (int mt = 0; mt < 4; mt++) {
                int r = wm + mt * 16 + lr;
                int c = ks + lc;
                af[mt][0] = __float_as_uint(as[r * AS_STRIDE + c]);
                af[mt][1] = __float_as_uint(as[(r + 8) * AS_STRIDE + c]);
                af[mt][2] = __float_as_uint(as[r * AS_STRIDE + c + 4]);
                af[mt][3] = __float_as_uint(as[(r + 8) * AS_STRIDE + c + 4]);
            }
#pragma unroll
            for (int nt = 0; nt < 4; nt++) {
                int n = wn + nt * 8 + lr;
                int c = ks + lc;
                bf[nt][0] = __float_as_uint(bs[c * BS_STRIDE + n]);
                bf[nt][1] = __float_as_uint(bs[(c + 4) * BS_STRIDE + n]);
            }
#pragma unroll
            for (int mt = 0; mt < 4; mt++)
#pragma unroll
                for (int nt = 0; nt < 4; nt++)
                    mma_tf32(acc[mt][nt], af[mt], bf[nt]);
        }
        __syncthreads();
    }

#pragma unroll
    for (int mt = 0; mt < 4; mt++) {
        int row = m0 + wm + mt * 16 + lr;
#pragma unroll
        for (int nt = 0; nt < 4; nt++) {
            int col = n0 + wn + nt * 8 + lc * 2;
#pragma unroll
            for (int half = 0; half < 2; half++) {
                int r = row + half * 8;
                float v0 = acc[mt][nt][half * 2 + 0];
                float v1 = acc[mt][nt][half * 2 + 1];
                if (bias)    { v0 += bias[col];        v1 += bias[col + 1]; }
                if (colbias) { v0 += colbias[col];     v1 += colbias[col + 1]; }
                if (act)     { v0 = gelu_f(v0);        v1 = gelu_f(v1); }
                if (residual) {
                    v0 += residual[(size_t)r * DMODEL + col];
                    v1 += residual[(size_t)r * DMODEL + col + 1];
                }
                if (rnd)     { v0 = to_tf32(v0);       v1 = to_tf32(v1); }
                float2 o; o.x = v0; o.y = v1;
                *(float2*)(Y + (size_t)r * DMODEL + col) = o;
            }
        }
    }
}

// ---------------- LayerNorm: warp per row, single pass, tf32-rounded output ----------------
__global__ void ln_kernel(const float* __restrict__ X, const float* __restrict__ g,
                          const float* __restrict__ b, float* __restrict__ Y) {
    int wid = threadIdx.x >> 5, lane = threadIdx.x & 31;
    int row = blockIdx.x * 8 + wid;
    const float4* X4 = (const float4*)(X + (size_t)row * DMODEL);
    const float4* G4 = (const float4*)g;
    const float4* B4 = (const float4*)b;
    float4* Y4 = (float4*)(Y + (size_t)row * DMODEL);

    float4 a = X4[lane];
    float4 c = X4[lane + 32];
    float s = a.x + a.y + a.z + a.w + c.x + c.y + c.z + c.w;
    float q = a.x * a.x + a.y * a.y + a.z * a.z + a.w * a.w
            + c.x * c.x + c.y * c.y + c.z * c.z + c.w * c.w;
#pragma unroll
    for (int o = 16; o > 0; o >>= 1) {
        s += __shfl_xor_sync(0xffffffffu, s, o);
        q += __shfl_xor_sync(0xffffffffu, q, o);
    }
    float mean = s * (1.0f / DMODEL);
    float var = q * (1.0f / DMODEL) - mean * mean;
    float rstd = rsqrtf(fmaxf(var, 0.f) + 1e-5f);

    float4 g1 = G4[lane], g2 = G4[lane + 32];
    float4 b1 = B4[lane], b2 = B4[lane + 32];
    float4 o1, o2;
    o1.x = to_tf32((a.x - mean) * rstd * g1.x + b1.x);
    o1.y = to_tf32((a.y - mean) * rstd * g1.y + b1.y);
    o1.z = to_tf32((a.z - mean) * rstd * g1.z + b1.z);
    o1.w = to_tf32((a.w - mean) * rstd * g1.w + b1.w);
    o2.x = to_tf32((c.x - mean) * rstd * g2.x + b2.x);
    o2.y = to_tf32((c.y - mean) * rstd * g2.y + b2.y);
    o2.z = to_tf32((c.z - mean) * rstd * g2.z + b2.z);
    o2.w = to_tf32((c.w - mean) * rstd * g2.w + b2.w);
    Y4[lane] = o1;
    Y4[lane + 32] = o2;
}

// ---------------- kvn: reduce 32 partials, normalize by S, split hi/lo ----------------
__global__ void kvn_kernel(const float* __restrict__ kvp, float* __restrict__ kvh,
                           float* __restrict__ kvl) {
    int idx = blockIdx.x * 256 + threadIdx.x;  // NH*QKDIM*DHEAD = 32768
    int he = idx >> 5, c = idx & 31;
    float sv = 0.f, ss = 0.f;
    const float* base = kvp + (size_t)he * 40;
#pragma unroll 4
    for (int b = 0; b < KVBLK; b++) {
        const float* p = base + (size_t)b * NH * QKDIM * 40;
        sv += p[c];
        ss += p[32];
    }
    float v = sv / ss;
    float hi = to_tf32(v);
    kvh[idx] = hi;
    kvl[idx] = to_tf32(v - hi);
}

// ================= tensor-core KV =================
// grid (32, NH), 1024 rows/block in 16 chunks of 64; partials out (no atomics)
#define KV_SMEM_FLOATS (32*136 + 32*44 + 64*36 + 128*68 + 64*44)
__global__ void kv_mma_kernel(const float* __restrict__ xm, const float* __restrict__ wk,
                              const float* __restrict__ wv, const float* __restrict__ temp_k,
                              float* __restrict__ kvp) {
    extern __shared__ float sm[];
    float* wk_s = sm;
    float* wv_s = wk_s + 32 * 136;
    float* xm_s = wv_s + 32 * 44;
    float* kT_s = xm_s + 64 * 36;
    float* v_s  = kT_s + 128 * 68;

    int h = blockIdx.y;
    int tid = threadIdx.x;
    int wid = tid >> 5, lane = tid & 31;
    int lr = lane >> 2, lc = lane & 3;

    for (int i = tid; i < 32 * 128; i += 256) {
        int k = i >> 7, e = i & 127;
        wk_s[k * 136 + e] = to_tf32(wk[k * 128 + e]);
    }
    for (int i = tid; i < 32 * 32; i += 256) {
        int k = i >> 5, c = i & 31;
        wv_s[k * 44 + c] = to_tf32(wv[k * 32 + c]);
    }
    float itk = 1.0f / fminf(fmaxf(temp_k[h], 0.1f), 2.0f);

    float kvacc[5][4];
#pragma unroll
    for (int i = 0; i < 5; i++)
#pragma unroll
        for (int j = 0; j < 4; j++) kvacc[i][j] = 0.f;

    int row0 = blockIdx.x * 1024;

    for (int ch = 0; ch < 16; ch++) {
        __syncthreads();
        {
            int r = tid >> 2, c0 = (tid & 3) * 8;
            const float* src = xm + (size_t)(row0 + ch * 64 + r) * DMODEL + h * DHEAD + c0;
            float4 v1 = *(const float4*)src, v2 = *(const float4*)(src + 4);
            float* dst = &xm_s[r * 36 + c0];
            dst[0] = v1.x; dst[1] = v1.y; dst[2] = v1.z; dst[3] = v1.w;
            dst[4] = v2.x; dst[5] = v2.y; dst[6] = v2.z; dst[7] = v2.w;
        }
        __syncthreads();

        {
            int wm = (wid & 3) * 16, wn = (wid >> 2) * 64;
            float acc[8][4];
#pragma unroll
            for (int i = 0; i < 8; i++)
#pragma unroll
                for (int j = 0; j < 4; j++) acc[i][j] = 0.f;
#pragma unroll
            for (int ks = 0; ks < 32; ks += 8) {
                uint32_t a[4];
                a[0] = __float_as_uint(xm_s[(wm + lr) * 36 + ks + lc]);
                a[1] = __float_as_uint(xm_s[(wm + lr + 8) * 36 + ks + lc]);
                a[2] = __float_as_uint(xm_s[(wm + lr) * 36 + ks + lc + 4]);
                a[3] = __float_as_uint(xm_s[(wm + lr + 8) * 36 + ks + lc + 4]);
#pragma unroll
                for (int nt = 0; nt < 8; nt++) {
                    uint32_t b[2];
                    b[0] = __float_as_uint(wk_s[(ks + lc) * 136 + wn + nt * 8 + lr]);
                    b[1] = __float_as_uint(wk_s[(ks + lc + 4) * 136 + wn + nt * 8 + lr]);
                    mma_tf32(acc[nt], a, b);
                }
            }
#pragma unroll
            for (int nt = 0; nt < 8; nt++) {
                int col = wn + nt * 8 + 2 * lc;
                int r = wm + lr;
                kT_s[col * 68 + r]           = to_tf32(__expf(acc[nt][0] * itk));
                kT_s[(col + 1) * 68 + r]     = to_tf32(__expf(acc[nt][1] * itk));
                kT_s[col * 68 + r + 8]       = to_tf32(__expf(acc[nt][2] * itk));
                kT_s[(col + 1) * 68 + r + 8] = to_tf32(__expf(acc[nt][3] * itk));
            }
        }
        if (wid < 4) {
            int wm = wid * 16;
            float acc[4][4];
#pragma unroll
            for (int i = 0; i < 4; i++)
#pragma unroll
                for (int j = 0; j < 4; j++) acc[i][j] = 0.f;
#pragma unroll
            for (int ks = 0; ks < 32; ks += 8) {
                uint32_t a[4];
                a[0] = __float_as_uint(xm_s[(wm + lr) * 36 + ks + lc]);
                a[1] = __float_as_uint(xm_s[(wm + lr + 8) * 36 + ks + lc]);
                a[2] = __float_as_uint(xm_s[(wm + lr) * 36 + ks + lc + 4]);
                a[3] = __float_as_uint(xm_s[(wm + lr + 8) * 36 + ks + lc + 4]);
#pragma unroll
                for (int nt = 0; nt < 4; nt++) {
                    uint32_t b[2];
                    b[0] = __float_as_uint(wv_s[(ks + lc) * 44 + nt * 8 + lr]);
                    b[1] = __float_as_uint(wv_s[(ks + lc + 4) * 44 + nt * 8 + lr]);
                    mma_tf32(acc[nt], a, b);
                }
            }
#pragma unroll
            for (int nt = 0; nt < 4; nt++) {
                int col = nt * 8 + 2 * lc;
                int r = wm + lr;
                v_s[r * 44 + col]           = to_tf32(acc[nt][0]);
                v_s[r * 44 + col + 1]       = to_tf32(acc[nt][1]);
                v_s[(r + 8) * 44 + col]     = to_tf32(acc[nt][2]);
                v_s[(r + 8) * 44 + col + 1] = to_tf32(acc[nt][3]);
            }
        }
        if (tid < 64) v_s[tid * 44 + 32] = 1.0f;
        __syncthreads();

        {
            int we = wid * 16;
#pragma unroll
            for (int ks = 0; ks < 64; ks += 8) {
                uint32_t a[4];
                a[0] = __float_as_uint(kT_s[(we + lr) * 68 + ks + lc]);
                a[1] = __float_as_uint(kT_s[(we + lr + 8) * 68 + ks + lc]);
                a[2] = __float_as_uint(kT_s[(we + lr) * 68 + ks + lc + 4]);
                a[3] = __float_as_uint(kT_s[(we + lr + 8) * 68 + ks + lc + 4]);
#pragma unroll
                for (int nt = 0; nt < 5; nt++) {
                    uint32_t b[2];
                    b[0] = __float_as_uint(v_s[(ks + lc) * 44 + nt * 8 + lr]);
                    b[1] = __float_as_uint(v_s[(ks + lc + 4) * 44 + nt * 8 + lr]);
                    mma_tf32(kvacc[nt], a, b);
                }
            }
        }
    }
    {   // flush partials (no atomics)
        float* dst = kvp + (size_t)(blockIdx.x * NH + h) * QKDIM * 40;
        int we = wid * 16;
#pragma unroll
        for (int nt = 0; nt < 5; nt++) {
            int col = nt * 8 + 2 * lc;
            int e0 = we + lr, e1 = we + lr + 8;
            if (col <= 32) {
                dst[e0 * 40 + col] = kvacc[nt][0];
                dst[e1 * 40 + col] = kvacc[nt][2];
            }
            if (col + 1 <= 32) {
                dst[e0 * 40 + col + 1] = kvacc[nt][1];
                dst[e1 * 40 + col + 1] = kvacc[nt][3];
            }
        }
    }
}

// ================= tensor-core QKV: 256 rows/block in 4 chunks =================
#define QKV_SMEM_FLOATS (128*36*2 + 32*136 + 64*36 + 64*132)
__global__ void qkv_mma_kernel(const float* __restrict__ xm, const float* __restrict__ wq,
                               const float* __restrict__ temp_q,
                               const float* __restrict__ kvhg, const float* __restrict__ kvlg,
                               float* __restrict__ out) {
    extern __shared__ float sm[];
    float* kvh  = sm;
    float* kvl  = kvh + 128 * 36;
    float* wq_s = kvl + 128 * 36;
    float* xm_s = wq_s + 32 * 136;
    float* q_s  = xm_s + 64 * 36;

    int h = blockIdx.y;
    int tid = threadIdx.x;
    int wid = tid >> 5, lane = tid & 31;
    int lr = lane >> 2, lc = lane & 3;

    for (int i = tid; i < 32 * 128; i += 256) {
        int k = i >> 7, e = i & 127;
        wq_s[k * 136 + e] = to_tf32(wq[k * 128 + e]);
    }
    {
        const float4* hsrc = (const float4*)(kvhg + h * QKDIM * DHEAD);
        const float4* lsrc = (const float4*)(kvlg + h * QKDIM * DHEAD);
        for (int i = tid; i < 1024; i += 256) {
            int e = i >> 3, c4 = (i & 7) * 4;
            float4 hv = hsrc[i], lv = lsrc[i];
            *(float4*)(&kvh[e * 36 + c4]) = hv;
            *(float4*)(&kvl[e * 36 + c4]) = lv;
        }
    }
    float itq = 1.0f / fminf(fmaxf(temp_q[h], 0.1f), 2.0f);

    for (int ch = 0; ch < 4; ch++) {
        int row0 = blockIdx.x * 256 + ch * 64;
        __syncthreads();
        {
            int r = tid >> 2, c0 = (tid & 3) * 8;
            const float* src = xm + (size_t)(row0 + r) * DMODEL + h * DHEAD + c0;
            float4 v1 = *(const float4*)src, v2 = *(const float4*)(src + 4);
            float* dst = &xm_s[r * 36 + c0];
            dst[0] = v1.x; dst[1] = v1.y; dst[2] = v1.z; dst[3] = v1.w;
            dst[4] = v2.x; dst[5] = v2.y; dst[6] = v2.z; dst[7] = v2.w;
        }
        __syncthreads();

        {
            int wm = (wid & 3) * 16, wn = (wid >> 2) * 64;
            float acc[8][4];
#pragma unroll
            for (int i = 0; i < 8; i++)
#pragma unroll
                for (int j = 0; j < 4; j++) acc[i][j] = 0.f;
#pragma unroll
            for (int ks = 0; ks < 32; ks += 8) {
                uint32_t a[4];
                a[0] = __float_as_uint(xm_s[(wm + lr) * 36 + ks + lc]);
                a[1] = __float_as_uint(xm_s[(wm + lr + 8) * 36 + ks + lc]);
                a[2] = __float_as_uint(xm_s[(wm + lr) * 36 + ks + lc + 4]);
                a[3] = __float_as_uint(xm_s[(wm + lr + 8) * 36 + ks + lc + 4]);
#pragma unroll
                for (int nt = 0; nt < 8; nt++) {
                    uint32_t b[2];
                    b[0] = __float_as_uint(wq_s[(ks + lc) * 136 + wn + nt * 8 + lr]);
                    b[1] = __float_as_uint(wq_s[(ks + lc + 4) * 136 + wn + nt * 8 + lr]);
                    mma_tf32(acc[nt], a, b);
                }
            }
#pragma unroll
            for (int nt = 0; nt < 8; nt++) {
                int col = wn + nt * 8 + 2 * lc;
                int r = wm + lr;
                q_s[r * 132 + col]           = acc[nt][0] * itq;
                q_s[r * 132 + col + 1]       = acc[nt][1] * itq;
                q_s[(r + 8) * 132 + col]     = acc[nt][2] * itq;
                q_s[(r + 8) * 132 + col + 1] = acc[nt][3] * itq;
            }
        }
        __syncthreads();
        {
            int r = tid >> 2, sub = tid & 3;
            float* row = q_s + r * 132;
            float mx = -1e30f;
#pragma unroll
            for (int k = 0; k < 32; k++) mx = fmaxf(mx, row[sub + k * 4]);
            mx = fmaxf(mx, __shfl_xor_sync(0xffffffffu, mx, 1));
            mx = fmaxf(mx, __shfl_xor_sync(0xffffffffu, mx, 2));
            float ev[32], sum = 0.f;
#pragma unroll
            for (int k = 0; k < 32; k++) { ev[k] = __expf(row[sub + k * 4] - mx); sum += ev[k]; }
            sum += __shfl_xor_sync(0xffffffffu, sum, 1);
            sum += __shfl_xor_sync(0xffffffffu, sum, 2);
            float inv = 1.0f / sum;
#pragma unroll
            for (int k = 0; k < 32; k++) row[sub + k * 4] = to_tf32(ev[k] * inv);
        }
        __syncthreads();
        {
            int wm = (wid & 3) * 16;
            int part = wid >> 2;
            const float* kvp = part ? kvl : kvh;
            float acc[4][4];
#pragma unroll
            for (int i = 0; i < 4; i++)
#pragma unroll
                for (int j = 0; j < 4; j++) acc[i][j] = 0.f;
#pragma unroll
            for (int ks = 0; ks < 128; ks += 8) {
                uint32_t a[4];
                a[0] = __float_as_uint(q_s[(wm + lr) * 132 + ks + lc]);
                a[1] = __float_as_uint(q_s[(wm + lr + 8) * 132 + ks + lc]);
                a[2] = __float_as_uint(q_s[(wm + lr) * 132 + ks + lc + 4]);
                a[3] = __float_as_uint(q_s[(wm + lr + 8) * 132 + ks + lc + 4]);
#pragma unroll
                for (int nt = 0; nt < 4; nt++) {
                    uint32_t b[2];
                    b[0] = __float_as_uint(kvp[(ks + lc) * 36 + nt * 8 + lr]);
                    b[1] = __float_as_uint(kvp[(ks + lc + 4) * 36 + nt * 8 + lr]);
                    mma_tf32(acc[nt], a, b);
                }
            }
            if (part == 1) {
#pragma unroll
                for (int nt = 0; nt < 4; nt++) {
                    int col = nt * 8 + 2 * lc;
                    int r = wm + lr;
                    xm_s[r * 36 + col]           = acc[nt][0];
                    xm_s[r * 36 + col + 1]       = acc[nt][1];
                    xm_s[(r + 8) * 36 + col]     = acc[nt][2];
                    xm_s[(r + 8) * 36 + col + 1] = acc[nt][3];
                }
            }
            __syncthreads();
            if (part == 0) {
#pragma unroll
                for (int nt = 0; nt < 4; nt++) {
                    int col = nt * 8 + 2 * lc;
#pragma unroll
                    for (int half = 0; half < 2; half++) {
                        int r = wm + lr + half * 8;
                        float v0 = to_tf32(acc[nt][half * 2 + 0] + xm_s[r * 36 + col]);
                        float v1 = to_tf32(acc[nt][half * 2 + 1] + xm_s[r * 36 + col + 1]);
                        float2 o; o.x = v0; o.y = v1;
                        *(float2*)(out + (size_t)(row0 + r) * DMODEL + h * DHEAD + col) = o;
                    }
                }
            }
        }
    }
}

// ---------------- head: warp per row ----------------
__global__ void head_kernel(const float* __restrict__ fx, const float* __restrict__ g,
                            const float* __restrict__ b, const float* __restrict__ hw,
                            const float* __restrict__ hb, float* __restrict__ out) {
    int wid = threadIdx.x >> 5, lane = threadIdx.x & 31;
    int row = blockIdx.x * 8 + wid;
    const float4* X4 = (const float4*)(fx + (size_t)row * DMODEL);
    const float4* G4 = (const float4*)g;
    const float4* B4 = (const float4*)b;
    const float4* H4 = (const float4*)hw;

    float4 a = X4[lane];
    float4 c = X4[lane + 32];
    float s = a.x + a.y + a.z + a.w + c.x + c.y + c.z + c.w;
    float q = a.x * a.x + a.y * a.y + a.z * a.z + a.w * a.w
            + c.x * c.x + c.y * c.y + c.z * c.z + c.w * c.w;
#pragma unroll
    for (int o = 16; o > 0; o >>= 1) {
        s += __shfl_xor_sync(0xffffffffu, s, o);
        q += __shfl_xor_sync(0xffffffffu, q, o);
    }
    float mean = s * (1.0f / DMODEL);
    float var = q * (1.0f / DMODEL) - mean * mean;
    float rstd = rsqrtf(fmaxf(var, 0.f) + 1e-5f);

    float4 g1 = G4[lane], g2 = G4[lane + 32];
    float4 b1 = B4[lane], b2 = B4[lane + 32];
    float4 h1 = H4[lane], h2 = H4[lane + 32];
    float dot =
        ((a.x - mean) * rstd * g1.x + b1.x) * h1.x +
        ((a.y - mean) * rstd * g1.y + b1.y) * h1.y +
        ((a.z - mean) * rstd * g1.z + b1.z) * h1.z +
        ((a.w - mean) * rstd * g1.w + b1.w) * h1.w +
        ((c.x - mean) * rstd * g2.x + b2.x) * h2.x +
        ((c.y - mean) * rstd * g2.y + b2.y) * h2.y +
        ((c.z - mean) * rstd * g2.z + b2.z) * h2.z +
        ((c.w - mean) * rstd * g2.w + b2.w) * h2.w;
#pragma unroll
    for (int o = 16; o > 0; o >>= 1) dot += __shfl_xor_sync(0xffffffffu, dot, o);
    if (lane == 0) out[row] = dot + hb[0];
}

// ---------------- launch ----------------
extern "C" void kernel_launch(void* const* d_in, const int* in_sizes, int n_in,
                              void* d_out, int out_size) {
    const float* x          = (const float*)d_in[0];
    const float* pre_w1     = (const float*)d_in[1];
    const float* pre_b1     = (const float*)d_in[2];
    const float* pre_w2     = (const float*)d_in[3];
    const float* pre_b2     = (const float*)d_in[4];
    const float* placeholder= (const float*)d_in[5];
    const float* ln1_g      = (const float*)d_in[6];
    const float* ln1_b      = (const float*)d_in[7];
    const float* inp_w      = (const float*)d_in[8];
    const float* inp_b      = (const float*)d_in[9];
    const float* temp_q     = (const float*)d_in[10];
    const float* temp_k     = (const float*)d_in[11];
    const float* wq         = (const float*)d_in[12];
    const float* wk         = (const float*)d_in[13];
    const float* wv         = (const float*)d_in[14];
    const float* out_w1     = (const float*)d_in[15];
    const float* out_b1     = (const float*)d_in[16];
    const float* out_w2     = (const float*)d_in[17];
    const float* out_b2     = (const float*)d_in[18];
    const float* ln2_g      = (const float*)d_in[19];
    const float* ln2_b      = (const float*)d_in[20];
    const float* mlp_w1     = (const float*)d_in[21];
    const float* mlp_b1     = (const float*)d_in[22];
    const float* mlp_w2     = (const float*)d_in[23];
    const float* mlp_b2     = (const float*)d_in[24];
    const float* ln3_g      = (const float*)d_in[25];
    const float* ln3_b      = (const float*)d_in[26];
    const float* head_w     = (const float*)d_in[27];
    const float* head_b     = (const float*)d_in[28];

    float *fx, *t1, *t2, *t3, *hidden, *kvp, *kvh, *kvl, *wc;
    cudaGetSymbolAddress((void**)&fx, g_fx);
    cudaGetSymbolAddress((void**)&t1, g_t1);
    cudaGetSymbolAddress((void**)&t2, g_t2);
    cudaGetSymbolAddress((void**)&t3, g_t3);
    cudaGetSymbolAddress((void**)&hidden, g_hidden);
    cudaGetSymbolAddress((void**)&kvp, g_kvp);
    cudaGetSymbolAddress((void**)&kvh, g_kvh);
    cudaGetSymbolAddress((void**)&kvl, g_kvl);
    cudaGetSymbolAddress((void**)&wc, g_wc);

    float* iwc   = wc;
    float* ow1c  = wc + 1 * WCONV_PER;
    float* ow2c  = wc + 2 * WCONV_PER;
    float* mw1c  = wc + 3 * WCONV_PER;
    float* mw2c  = wc + 4 * WCONV_PER;
    float* pw2c  = wc + 5 * WCONV_PER;

    const int gemm_smem = GEMM_SMEM_FLOATS * 4;
    const int kv_smem = KV_SMEM_FLOATS * 4;
    const int qkv_smem = QKV_SMEM_FLOATS * 4;
    cudaFuncSetAttribute(gemm_kernel, cudaFuncAttributeMaxDynamicSharedMemorySize, gemm_smem);
    cudaFuncSetAttribute(kv_mma_kernel, cudaFuncAttributeMaxDynamicSharedMemorySize, kv_smem);
    cudaFuncSetAttribute(qkv_mma_kernel, cudaFuncAttributeMaxDynamicSharedMemorySize, qkv_smem);

    dim3 ggrid(NPTS / TBM, DMODEL / TBN);

    conv6_tf32_kernel<<<dim3((WCONV_PER / 4 + 255) / 256, 6), 256>>>(inp_w, out_w1, out_w2,
                                                                     mlp_w1, mlp_w2, pre_w2, wc);

    pre1_kernel<<<NPTS * 512 / 256, 256>>>(x, pre_w1, pre_b1, hidden);
    gemm_kernel<<<ggrid, 256, gemm_smem>>>(hidden, 512, pw2c, pre_b2, placeholder, nullptr, fx, 0, 0);

    for (int i = 0; i < NLAYERS; i++) {
        const float* iw  = iwc  + (size_t)i * 65536;
        const float* ow1 = ow1c + (size_t)i * 65536;
        const float* ow2 = ow2c + (size_t)i * 65536;
        const float* mw1 = mw1c + (size_t)i * 65536;
        const float* mw2 = mw2c + (size_t)i * 65536;

        ln_kernel<<<NPTS / 8, 256>>>(fx, ln1_g + i * 256, ln1_b + i * 256, t1);
        gemm_kernel<<<ggrid, 256, gemm_smem>>>(t1, 256, iw, inp_b + i * 256, nullptr, nullptr, t2, 0, 1);
        kv_mma_kernel<<<dim3(KVBLK, NH), 256, kv_smem>>>(t2, wk + (size_t)i * 4096,
                                                         wv + (size_t)i * 1024, temp_k + i * NH, kvp);
        kvn_kernel<<<(NH * QKDIM * DHEAD + 255) / 256, 256>>>(kvp, kvh, kvl);
        qkv_mma_kernel<<<dim3(NPTS / 256, NH), 256, qkv_smem>>>(t2, wq + (size_t)i * 4096,
                                                                temp_q + i * NH, kvh, kvl, t3);
        gemm_kernel<<<ggrid, 256, gemm_smem>>>(t3, 256, ow1, out_b1 + i * 256, nullptr, nullptr, t1, 1, 1);
        gemm_kernel<<<ggrid, 256, gemm_smem>>>(t1, 256, ow2, out_b2 + i * 256, nullptr, fx, fx, 0, 0);
        ln_kernel<<<NPTS / 8, 256>>>(fx, ln2_g + i * 256, ln2_b + i * 256, t1);
        gemm_kernel<<<ggrid, 256, gemm_smem>>>(t1, 256, mw1, mlp_b1 + i * 256, nullptr, nullptr, t2, 1, 1);
        gemm_kernel<<<ggrid, 256, gemm_smem>>>(t2, 256, mw2, mlp_b2 + i * 256, nullptr, fx, fx, 0, 0);
    }
    head_kernel<<<NPTS / 8, 256>>>(fx, ln3_g, ln3_b, head_w, head_b, (float*)d_out);
}